// round 1
// baseline (speedup 1.0000x reference)
#include <cuda_runtime.h>
#include <math.h>

// ---------------- problem constants ----------------
#define NLAYERS 6
#define BATCH   2
#define LSEQ    1024
#define DMODEL  512
#define EINNER  1024
#define NSTATE  16
#define RRANK   32
#define RBC     64            // RRANK + 2*NSTATE
#define TTOK    (BATCH*LSEQ)  // 2048
#define NCHUNK  8
#define TCH     (LSEQ/NCHUNK) // 128
#define EPSF    1.1920929e-07f

// ---------------- scratch (device globals; no mallocs allowed) ----------------
__device__ float g_h   [TTOK*DMODEL];
__device__ float g_xn  [TTOK*DMODEL];
__device__ float g_xz  [TTOK*2*EINNER];
__device__ float g_xi  [TTOK*EINNER];
__device__ float g_dbcp[8*TTOK*RBC];
__device__ float g_dbc [TTOK*RBC];
__device__ float g_dt  [TTOK*EINNER];
__device__ float g_y   [TTOK*EINNER];
__device__ float g_hN  [BATCH*NCHUNK*EINNER*NSTATE];
__device__ float g_P   [BATCH*NCHUNK*EINNER*NSTATE];
__device__ float g_S   [BATCH*NCHUNK*EINNER*NSTATE];

// ---------------- fast exp on the FMA pipe (no MUFU) ----------------
// exp(x) = 2^(x*log2e); magic-number rint, degree-5 poly for 2^r, r in [-0.5,0.5].
// rel err ~2e-6. Clamped for safety (inputs are dt*A <= 0, sums can be very negative).
__device__ __forceinline__ float fexp(float x) {
    x = fminf(fmaxf(x, -80.0f), 80.0f);
    float f = x * 1.4426950408889634f;
    float t = f + 12582912.0f;                  // 1.5*2^23
    int   i = __float_as_int(t) - 0x4B400000;   // rint(f) as int
    float r = f - (t - 12582912.0f);            // [-0.5, 0.5]
    float p =          1.3333558e-3f;
    p = fmaf(p, r, 9.6181291e-3f);
    p = fmaf(p, r, 5.5504109e-2f);
    p = fmaf(p, r, 2.4022651e-1f);
    p = fmaf(p, r, 6.9314718e-1f);
    p = fmaf(p, r, 1.0f);
    return __int_as_float(__float_as_int(p) + (i << 23));
}

__device__ __forceinline__ float softplusf(float x) {
    return fmaxf(x, 0.0f) + log1pf(__expf(-fabsf(x)));
}

// ---------------- K1: h+pos then RMSNorm ----------------
__global__ void k_addnorm(const float* __restrict__ hin, const float* __restrict__ pos,
                          const float* __restrict__ nw, float* __restrict__ out) {
    int t = blockIdx.x;           // token
    int tid = threadIdx.x;        // 128 threads * float4 = 512
    float4 v  = ((const float4*)(hin + t*DMODEL))[tid];
    float4 pv = ((const float4*)(pos + t*DMODEL))[tid];
    v.x += pv.x; v.y += pv.y; v.z += pv.z; v.w += pv.w;
    float ss = v.x*v.x + v.y*v.y + v.z*v.z + v.w*v.w;
    #pragma unroll
    for (int o = 16; o > 0; o >>= 1) ss += __shfl_xor_sync(0xffffffffu, ss, o);
    __shared__ float sred[4];
    if ((tid & 31) == 0) sred[tid >> 5] = ss;
    __syncthreads();
    ss = sred[0] + sred[1] + sred[2] + sred[3];
    float s = rsqrtf(ss * (1.0f/DMODEL) + EPSF);
    float4 w = ((const float4*)nw)[tid];
    float4 o4;
    o4.x = v.x*s*w.x; o4.y = v.y*s*w.y; o4.z = v.z*s*w.z; o4.w = v.w*s*w.w;
    ((float4*)(out + t*DMODEL))[tid] = o4;
}

// ---------------- generic fp32 NT GEMM: C[m,n] = sum_k A[m,k]*W[n,k] ----------------
// 64x64 tile, BK=16, 256 threads, 4x4 per thread. grid.z = split-K (writes partials).
// EPI: 0 = plain store, 1 = softplus(acc + bias[n]).
template<int EPI>
__global__ void k_gemm(const float* __restrict__ A, const float* __restrict__ W,
                       float* __restrict__ C, int M, int N, int K,
                       int lda, int ldw, int ldc,
                       const float* __restrict__ bias, int pstride)
{
    __shared__ float As[16][64];
    __shared__ float Ws[16][64];
    int tid = threadIdx.x;
    int m0 = blockIdx.y * 64, n0 = blockIdx.x * 64;
    int kLen = K / gridDim.z;
    int k0 = blockIdx.z * kLen;
    int row = tid >> 2, kq = tid & 3;
    const float* Ap = A + (size_t)(m0 + row) * lda + k0 + kq * 4;
    const float* Wp = W + (size_t)(n0 + row) * ldw + k0 + kq * 4;
    int tx = (tid & 15) * 4, ty = (tid >> 4) * 4;
    float acc[4][4];
    #pragma unroll
    for (int i = 0; i < 4; i++)
        #pragma unroll
        for (int j = 0; j < 4; j++) acc[i][j] = 0.0f;

    for (int kt = 0; kt < kLen; kt += 16) {
        float4 av = *(const float4*)(Ap + kt);
        float4 wv = *(const float4*)(Wp + kt);
        __syncthreads();
        As[kq*4+0][row] = av.x; As[kq*4+1][row] = av.y;
        As[kq*4+2][row] = av.z; As[kq*4+3][row] = av.w;
        Ws[kq*4+0][row] = wv.x; Ws[kq*4+1][row] = wv.y;
        Ws[kq*4+2][row] = wv.z; Ws[kq*4+3][row] = wv.w;
        __syncthreads();
        #pragma unroll
        for (int kk = 0; kk < 16; kk++) {
            float4 a = *(const float4*)&As[kk][ty];
            float4 w = *(const float4*)&Ws[kk][tx];
            float ar[4] = {a.x, a.y, a.z, a.w};
            float wr[4] = {w.x, w.y, w.z, w.w};
            #pragma unroll
            for (int i = 0; i < 4; i++)
                #pragma unroll
                for (int j = 0; j < 4; j++)
                    acc[i][j] = fmaf(ar[i], wr[j], acc[i][j]);
        }
    }

    float* Cp = C + (size_t)blockIdx.z * pstride;
    float4 bv = make_float4(0.f, 0.f, 0.f, 0.f);
    if (EPI == 1) bv = *(const float4*)&bias[n0 + tx];
    #pragma unroll
    for (int i = 0; i < 4; i++) {
        int m = m0 + ty + i;
        float4 o;
        if (EPI == 1) {
            o.x = softplusf(acc[i][0] + bv.x);
            o.y = softplusf(acc[i][1] + bv.y);
            o.z = softplusf(acc[i][2] + bv.z);
            o.w = softplusf(acc[i][3] + bv.w);
        } else {
            o.x = acc[i][0]; o.y = acc[i][1]; o.z = acc[i][2]; o.w = acc[i][3];
        }
        *(float4*)(Cp + (size_t)m * ldc + n0 + tx) = o;
    }
}

// ---------------- K3: causal depthwise conv (k=4) + bias + SiLU ----------------
__global__ void k_conv(const float* __restrict__ xz, const float* __restrict__ cw,
                       const float* __restrict__ cb, float* __restrict__ xi) {
    int idx = blockIdx.x * blockDim.x + threadIdx.x;   // over B*L*E
    int e = idx & (EINNER - 1);
    int l = (idx >> 10) & (LSEQ - 1);
    int b = idx >> 20;
    float acc = cb[e];
    const float* base = xz + (size_t)(b * LSEQ) * 2 * EINNER + e;
    #pragma unroll
    for (int k = 0; k < 4; k++) {
        int li = l - 3 + k;
        if (li >= 0) acc = fmaf(cw[e*4 + k], base[(size_t)li * 2 * EINNER], acc);
    }
    xi[idx] = acc / (1.0f + __expf(-acc));   // SiLU
}

// ---------------- split-K reduce for x_proj ----------------
__global__ void k_reduce8(const float* __restrict__ part, float* __restrict__ out, int n) {
    int i = blockIdx.x * blockDim.x + threadIdx.x;
    if (i < n) {
        float s = 0.f;
        #pragma unroll
        for (int z = 0; z < 8; z++) s += part[(size_t)z * n + i];
        out[i] = s;
    }
}

// ---------------- scan pass 1: per-chunk local state (h0=0) + chunk decay P ----------------
__global__ void k_scan1(const float* __restrict__ dt, const float* __restrict__ u,
                        const float* __restrict__ dbc, const float* __restrict__ Alog,
                        float* __restrict__ hN, float* __restrict__ P) {
    int e = blockIdx.x * 128 + threadIdx.x;
    int c = blockIdx.y, b = blockIdx.z;
    float A[NSTATE];
    #pragma unroll
    for (int n = 0; n < NSTATE; n++) A[n] = -__expf(Alog[e*NSTATE + n]);
    float h[NSTATE];
    #pragma unroll
    for (int n = 0; n < NSTATE; n++) h[n] = 0.f;
    float dts = 0.f;
    int rowbase = b * LSEQ + c * TCH;
    for (int tt = 0; tt < TCH; tt++) {
        int row = rowbase + tt;
        float d  = dt[(size_t)row * EINNER + e];
        float uu = u [(size_t)row * EINNER + e];
        float du = d * uu;
        const float* bc = dbc + (size_t)row * RBC + RRANK;
        #pragma unroll
        for (int n = 0; n < NSTATE; n++) {
            float a = fexp(d * A[n]);
            h[n] = fmaf(a, h[n], du * bc[n]);
        }
        dts += d;
    }
    int o = ((b * NCHUNK + c) * EINNER + e) * NSTATE;
    #pragma unroll
    for (int n = 0; n < NSTATE; n++) {
        hN[o + n] = h[n];
        P[o + n]  = fexp(dts * A[n]);   // prod_t exp(dt_t*A_n) = exp(A_n * sum dt)
    }
}

// ---------------- scan pass 2: sequential chunk combine (tiny) ----------------
__global__ void k_scan2(const float* __restrict__ hN, const float* __restrict__ P,
                        float* __restrict__ S) {
    int idx = blockIdx.x * blockDim.x + threadIdx.x;  // B*E*NSTATE = 32768
    int b = idx >> 14;                                // E*NSTATE = 16384
    int r = idx & 16383;
    float s = 0.f;
    int base = b * NCHUNK * EINNER * NSTATE + r;
    #pragma unroll
    for (int c = 0; c < NCHUNK; c++) {
        S[base + c * EINNER * NSTATE] = s;
        s = hN[base + c * EINNER * NSTATE] + P[base + c * EINNER * NSTATE] * s;
    }
}

// ---------------- scan pass 3: full scan with correct init state + y + D skip + gate ----------------
__global__ void k_scan3(const float* __restrict__ dt, const float* __restrict__ u,
                        const float* __restrict__ dbc, const float* __restrict__ xz,
                        const float* __restrict__ Alog, const float* __restrict__ Dv,
                        const float* __restrict__ S, float* __restrict__ y) {
    int e = blockIdx.x * 128 + threadIdx.x;
    int c = blockIdx.y, b = blockIdx.z;
    float A[NSTATE];
    #pragma unroll
    for (int n = 0; n < NSTATE; n++) A[n] = -__expf(Alog[e*NSTATE + n]);
    float Dd = Dv[e];
    float h[NSTATE];
    int o = ((b * NCHUNK + c) * EINNER + e) * NSTATE;
    #pragma unroll
    for (int n = 0; n < NSTATE; n++) h[n] = S[o + n];
    int rowbase = b * LSEQ + c * TCH;
    for (int tt = 0; tt < TCH; tt++) {
        int row = rowbase + tt;
        float d  = dt[(size_t)row * EINNER + e];
        float uu = u [(size_t)row * EINNER + e];
        float zz = xz[(size_t)row * 2 * EINNER + EINNER + e];
        float du = d * uu;
        const float* bc = dbc + (size_t)row * RBC + RRANK;
        float acc = 0.f;
        #pragma unroll
        for (int n = 0; n < NSTATE; n++) {
            float a = fexp(d * A[n]);
            h[n] = fmaf(a, h[n], du * bc[n]);
            acc = fmaf(h[n], bc[NSTATE + n], acc);
        }
        acc = fmaf(uu, Dd, acc);
        float sz = zz / (1.0f + fexp(-zz));   // silu(z)
        y[(size_t)row * EINNER + e] = acc * sz;
    }
}

// ---------------- launcher ----------------
extern "C" void kernel_launch(void* const* d_in, const int* in_sizes, int n_in,
                              void* d_out, int out_size) {
    const float* x     = (const float*)d_in[0];
    const float* pos   = (const float*)d_in[1];
    const float* normw = (const float*)d_in[2];
    const float* inw   = (const float*)d_in[3];
    const float* convw = (const float*)d_in[4];
    const float* convb = (const float*)d_in[5];
    const float* xpw   = (const float*)d_in[6];
    const float* dtw   = (const float*)d_in[7];
    const float* dtb   = (const float*)d_in[8];
    const float* alog  = (const float*)d_in[9];
    const float* dvec  = (const float*)d_in[10];
    const float* outw  = (const float*)d_in[11];
    float* out = (float*)d_out;
    (void)in_sizes; (void)n_in; (void)out_size;

    float *ph, *pxn, *pxz, *pxi, *pdbcp, *pdbc, *pdt, *py, *phN, *pP, *pS;
    cudaGetSymbolAddress((void**)&ph,    g_h);
    cudaGetSymbolAddress((void**)&pxn,   g_xn);
    cudaGetSymbolAddress((void**)&pxz,   g_xz);
    cudaGetSymbolAddress((void**)&pxi,   g_xi);
    cudaGetSymbolAddress((void**)&pdbcp, g_dbcp);
    cudaGetSymbolAddress((void**)&pdbc,  g_dbc);
    cudaGetSymbolAddress((void**)&pdt,   g_dt);
    cudaGetSymbolAddress((void**)&py,    g_y);
    cudaGetSymbolAddress((void**)&phN,   g_hN);
    cudaGetSymbolAddress((void**)&pP,    g_P);
    cudaGetSymbolAddress((void**)&pS,    g_S);

    for (int l = 0; l < NLAYERS; l++) {
        const float* hin = (l == 0) ? x : ph;
        // 1. h+pos -> rmsnorm -> xn
        k_addnorm<<<TTOK, 128>>>(hin, pos, normw, pxn);
        // 2. in_proj: (2048,512) x (2048,512)^T -> xz (2048,2048)
        k_gemm<0><<<dim3(32, 32, 1), 256>>>(pxn, inw + (size_t)l*2*EINNER*DMODEL, pxz,
                                            TTOK, 2*EINNER, DMODEL, DMODEL, DMODEL, 2*EINNER,
                                            nullptr, 0);
        // 3. depthwise causal conv + SiLU -> xi
        k_conv<<<(TTOK*EINNER)/256, 256>>>(pxz, convw + (size_t)l*EINNER*4,
                                           convb + (size_t)l*EINNER, pxi);
        // 4. x_proj with split-K=8 partials, then reduce -> dbc (2048,64)
        k_gemm<0><<<dim3(1, 32, 8), 256>>>(pxi, xpw + (size_t)l*RBC*EINNER, pdbcp,
                                           TTOK, RBC, EINNER, EINNER, EINNER, RBC,
                                           nullptr, TTOK*RBC);
        k_reduce8<<<(TTOK*RBC)/256, 256>>>(pdbcp, pdbc, TTOK*RBC);
        // 5. dt_proj + softplus(+bias) -> dt (2048,1024)
        k_gemm<1><<<dim3(16, 32, 1), 256>>>(pdbc, dtw + (size_t)l*EINNER*RRANK, pdt,
                                            TTOK, EINNER, RRANK, RBC, RRANK, EINNER,
                                            dtb + (size_t)l*EINNER, 0);
        // 6. chunked selective scan (3 passes), fused with D skip + silu(z) gate
        k_scan1<<<dim3(EINNER/128, NCHUNK, BATCH), 128>>>(pdt, pxi, pdbc,
                                                          alog + (size_t)l*EINNER*NSTATE,
                                                          phN, pP);
        k_scan2<<<(BATCH*EINNER*NSTATE)/256, 256>>>(phN, pP, pS);
        k_scan3<<<dim3(EINNER/128, NCHUNK, BATCH), 128>>>(pdt, pxi, pdbc, pxz,
                                                          alog + (size_t)l*EINNER*NSTATE,
                                                          dvec + (size_t)l*EINNER, pS, py);
        // 7. out_proj -> next h (or final output)
        float* dest = (l == NLAYERS-1) ? out : ph;
        k_gemm<0><<<dim3(8, 32, 1), 256>>>(py, outw + (size_t)l*DMODEL*EINNER, dest,
                                           TTOK, DMODEL, EINNER, EINNER, EINNER, DMODEL,
                                           nullptr, 0);
    }
}

// round 2
// speedup vs baseline: 1.4407x; 1.4407x over previous
#include <cuda_runtime.h>
#include <cuda_bf16.h>
#include <math.h>

// ---------------- problem constants ----------------
#define NLAYERS 6
#define BATCH   2
#define LSEQ    1024
#define DMODEL  512
#define EINNER  1024
#define NSTATE  16
#define RRANK   32
#define RBC     64            // RRANK + 2*NSTATE
#define TTOK    (BATCH*LSEQ)  // 2048
#define NCHUNK  8
#define TCH     (LSEQ/NCHUNK) // 128
#define EPSF    1.1920929e-07f

// ---------------- scratch (device globals; no mallocs allowed) ----------------
__device__ float g_h   [TTOK*DMODEL];
__device__ float g_xn  [TTOK*DMODEL];
__device__ float g_xz  [TTOK*2*EINNER];
__device__ float g_xi  [TTOK*EINNER];
__device__ float g_dbcp[8*TTOK*RBC];
__device__ float g_dbc [TTOK*RBC];
__device__ float g_dt  [TTOK*EINNER];
__device__ float g_y   [TTOK*EINNER];
__device__ float g_hN  [BATCH*NCHUNK*EINNER*NSTATE];
__device__ float g_P   [BATCH*NCHUNK*EINNER*NSTATE];
__device__ float g_S   [BATCH*NCHUNK*EINNER*NSTATE];

// ---------------- fast exp on the FMA pipe (no MUFU) ----------------
__device__ __forceinline__ float fexp(float x) {
    x = fminf(fmaxf(x, -80.0f), 80.0f);
    float f = x * 1.4426950408889634f;
    float t = f + 12582912.0f;                  // 1.5*2^23
    int   i = __float_as_int(t) - 0x4B400000;   // rint(f) as int
    float r = f - (t - 12582912.0f);            // [-0.5, 0.5]
    float p =          1.3333558e-3f;
    p = fmaf(p, r, 9.6181291e-3f);
    p = fmaf(p, r, 5.5504109e-2f);
    p = fmaf(p, r, 2.4022651e-1f);
    p = fmaf(p, r, 6.9314718e-1f);
    p = fmaf(p, r, 1.0f);
    return __int_as_float(__float_as_int(p) + (i << 23));
}

__device__ __forceinline__ float softplusf(float x) {
    return fmaxf(x, 0.0f) + log1pf(__expf(-fabsf(x)));
}

// ---------------- K1: h+pos then RMSNorm ----------------
__global__ void k_addnorm(const float* __restrict__ hin, const float* __restrict__ pos,
                          const float* __restrict__ nw, float* __restrict__ out) {
    int t = blockIdx.x;
    int tid = threadIdx.x;        // 128 threads * float4 = 512
    float4 v  = ((const float4*)(hin + t*DMODEL))[tid];
    float4 pv = ((const float4*)(pos + t*DMODEL))[tid];
    v.x += pv.x; v.y += pv.y; v.z += pv.z; v.w += pv.w;
    float ss = v.x*v.x + v.y*v.y + v.z*v.z + v.w*v.w;
    #pragma unroll
    for (int o = 16; o > 0; o >>= 1) ss += __shfl_xor_sync(0xffffffffu, ss, o);
    __shared__ float sred[4];
    if ((tid & 31) == 0) sred[tid >> 5] = ss;
    __syncthreads();
    ss = sred[0] + sred[1] + sred[2] + sred[3];
    float s = rsqrtf(ss * (1.0f/DMODEL) + EPSF);
    float4 w = ((const float4*)nw)[tid];
    float4 o4;
    o4.x = v.x*s*w.x; o4.y = v.y*s*w.y; o4.z = v.z*s*w.z; o4.w = v.w*s*w.w;
    ((float4*)(out + t*DMODEL))[tid] = o4;
}

// ---------------- bf16 split MMA GEMM ----------------
// C[m,n] = sum_k A[m,k]*W[n,k], fp32 in/out, computed as 3-term bf16-split:
// a*b ~= ah*bh + ah*bl + al*bh  (al = a - bf16(a)). Accuracy ~2^-17 relative.
// EPI: 0 = plain store, 1 = softplus(acc + bias[n]). grid.z = split-K partials.
__device__ __forceinline__ void mma_bf16(float (&d)[4], const unsigned (&a)[4],
                                         const unsigned (&b)[2]) {
    asm volatile(
        "mma.sync.aligned.m16n8k16.row.col.f32.bf16.bf16.f32 "
        "{%0,%1,%2,%3}, {%4,%5,%6,%7}, {%8,%9}, {%0,%1,%2,%3};\n"
        : "+f"(d[0]), "+f"(d[1]), "+f"(d[2]), "+f"(d[3])
        : "r"(a[0]), "r"(a[1]), "r"(a[2]), "r"(a[3]), "r"(b[0]), "r"(b[1]));
}

template<int BM, int BN, int WARPS_M, int WARPS_N, int EPI>
__global__ void __launch_bounds__(WARPS_M*WARPS_N*32)
k_mma(const float* __restrict__ A, const float* __restrict__ W,
      float* __restrict__ C, int M, int N, int K,
      int lda, int ldw, int ldc,
      const float* __restrict__ bias, int pstride)
{
    constexpr int BK = 32;
    constexpr int THREADS = WARPS_M*WARPS_N*32;
    constexpr int WM = BM/WARPS_M, WN = BN/WARPS_N;
    constexpr int TM = WM/16, TN = WN/8;
    constexpr int LST = BK + 8;                    // smem row stride in bf16 (80B)
    constexpr int LOADS_A = BM*(BK/4)/THREADS;     // float4 per thread
    constexpr int LOADS_B = BN*(BK/4)/THREADS;

    __shared__ __nv_bfloat16 Ah[BM*LST], Al[BM*LST];
    __shared__ __nv_bfloat16 Bh[BN*LST], Bl[BN*LST];

    const int tid  = threadIdx.x;
    const int lane = tid & 31;
    const int warp = tid >> 5;
    const int wm = (warp / WARPS_N) * WM;
    const int wn = (warp % WARPS_N) * WN;
    const int m0 = blockIdx.y * BM, n0 = blockIdx.x * BN;
    const int kLen = K / gridDim.z;
    const int k0 = blockIdx.z * kLen;
    const int niter = kLen / BK;

    float acc[TM][TN][4];
    #pragma unroll
    for (int i = 0; i < TM; i++)
        #pragma unroll
        for (int j = 0; j < TN; j++)
            #pragma unroll
            for (int q = 0; q < 4; q++) acc[i][j][q] = 0.0f;

    float4 stA[LOADS_A], stB[LOADS_B];

    // prologue: load tile 0
    #pragma unroll
    for (int i = 0; i < LOADS_A; i++) {
        int c = tid + i*THREADS; int r = c >> 3, kc = c & 7;
        stA[i] = *(const float4*)&A[(size_t)(m0 + r) * lda + k0 + kc*4];
    }
    #pragma unroll
    for (int i = 0; i < LOADS_B; i++) {
        int c = tid + i*THREADS; int r = c >> 3, kc = c & 7;
        stB[i] = *(const float4*)&W[(size_t)(n0 + r) * ldw + k0 + kc*4];
    }

    for (int kt = 0; kt < niter; kt++) {
        __syncthreads();
        // convert + store staged tile to smem (hi/lo planes)
        #pragma unroll
        for (int i = 0; i < LOADS_A; i++) {
            int c = tid + i*THREADS; int r = c >> 3, kc = c & 7;
            float v[4] = {stA[i].x, stA[i].y, stA[i].z, stA[i].w};
            int off = r*LST + kc*4;
            #pragma unroll
            for (int q = 0; q < 4; q += 2) {
                __nv_bfloat16 h0 = __float2bfloat16(v[q]);
                __nv_bfloat16 h1 = __float2bfloat16(v[q+1]);
                __nv_bfloat16 l0 = __float2bfloat16(v[q]   - __bfloat162float(h0));
                __nv_bfloat16 l1 = __float2bfloat16(v[q+1] - __bfloat162float(h1));
                *(__nv_bfloat162*)&Ah[off+q] = __nv_bfloat162(h0, h1);
                *(__nv_bfloat162*)&Al[off+q] = __nv_bfloat162(l0, l1);
            }
        }
        #pragma unroll
        for (int i = 0; i < LOADS_B; i++) {
            int c = tid + i*THREADS; int r = c >> 3, kc = c & 7;
            float v[4] = {stB[i].x, stB[i].y, stB[i].z, stB[i].w};
            int off = r*LST + kc*4;
            #pragma unroll
            for (int q = 0; q < 4; q += 2) {
                __nv_bfloat16 h0 = __float2bfloat16(v[q]);
                __nv_bfloat16 h1 = __float2bfloat16(v[q+1]);
                __nv_bfloat16 l0 = __float2bfloat16(v[q]   - __bfloat162float(h0));
                __nv_bfloat16 l1 = __float2bfloat16(v[q+1] - __bfloat162float(h1));
                *(__nv_bfloat162*)&Bh[off+q] = __nv_bfloat162(h0, h1);
                *(__nv_bfloat162*)&Bl[off+q] = __nv_bfloat162(l0, l1);
            }
        }
        __syncthreads();

        // prefetch next tile into regs (overlaps with mma below)
        if (kt + 1 < niter) {
            int kb = k0 + (kt+1)*BK;
            #pragma unroll
            for (int i = 0; i < LOADS_A; i++) {
                int c = tid + i*THREADS; int r = c >> 3, kc = c & 7;
                stA[i] = *(const float4*)&A[(size_t)(m0 + r) * lda + kb + kc*4];
            }
            #pragma unroll
            for (int i = 0; i < LOADS_B; i++) {
                int c = tid + i*THREADS; int r = c >> 3, kc = c & 7;
                stB[i] = *(const float4*)&W[(size_t)(n0 + r) * ldw + kb + kc*4];
            }
        }

        // compute: 2 x k16 steps, 3 bf16 terms each
        #pragma unroll
        for (int s = 0; s < 2; s++) {
            const int kb = s*16 + (lane & 3)*2;
            unsigned bh[TN][2], bl[TN][2];
            #pragma unroll
            for (int j = 0; j < TN; j++) {
                int nb = (wn + j*8 + (lane >> 2)) * LST;
                bh[j][0] = *(const unsigned*)&Bh[nb + kb];
                bh[j][1] = *(const unsigned*)&Bh[nb + kb + 8];
                bl[j][0] = *(const unsigned*)&Bl[nb + kb];
                bl[j][1] = *(const unsigned*)&Bl[nb + kb + 8];
            }
            #pragma unroll
            for (int i = 0; i < TM; i++) {
                int mb = (wm + i*16 + (lane >> 2)) * LST;
                unsigned ah[4], al[4];
                ah[0] = *(const unsigned*)&Ah[mb + kb];
                ah[1] = *(const unsigned*)&Ah[mb + 8*LST + kb];
                ah[2] = *(const unsigned*)&Ah[mb + kb + 8];
                ah[3] = *(const unsigned*)&Ah[mb + 8*LST + kb + 8];
                al[0] = *(const unsigned*)&Al[mb + kb];
                al[1] = *(const unsigned*)&Al[mb + 8*LST + kb];
                al[2] = *(const unsigned*)&Al[mb + kb + 8];
                al[3] = *(const unsigned*)&Al[mb + 8*LST + kb + 8];
                #pragma unroll
                for (int j = 0; j < TN; j++) {
                    mma_bf16(acc[i][j], ah, bh[j]);
                    mma_bf16(acc[i][j], ah, bl[j]);
                    mma_bf16(acc[i][j], al, bh[j]);
                }
            }
        }
    }

    // epilogue
    float* Cp = C + (size_t)blockIdx.z * pstride;
    #pragma unroll
    for (int i = 0; i < TM; i++) {
        int row = m0 + wm + i*16 + (lane >> 2);
        #pragma unroll
        for (int j = 0; j < TN; j++) {
            int col = n0 + wn + j*8 + (lane & 3)*2;
            float2 v0, v1;
            if (EPI == 1) {
                float b0 = bias[col], b1 = bias[col+1];
                v0.x = softplusf(acc[i][j][0] + b0);
                v0.y = softplusf(acc[i][j][1] + b1);
                v1.x = softplusf(acc[i][j][2] + b0);
                v1.y = softplusf(acc[i][j][3] + b1);
            } else {
                v0.x = acc[i][j][0]; v0.y = acc[i][j][1];
                v1.x = acc[i][j][2]; v1.y = acc[i][j][3];
            }
            *(float2*)&Cp[(size_t)row * ldc + col]       = v0;
            *(float2*)&Cp[(size_t)(row+8) * ldc + col]   = v1;
        }
    }
}

// ---------------- K3: causal depthwise conv (k=4) + bias + SiLU ----------------
__global__ void k_conv(const float* __restrict__ xz, const float* __restrict__ cw,
                       const float* __restrict__ cb, float* __restrict__ xi) {
    int idx = blockIdx.x * blockDim.x + threadIdx.x;   // over B*L*E
    int e = idx & (EINNER - 1);
    int l = (idx >> 10) & (LSEQ - 1);
    int b = idx >> 20;
    float acc = cb[e];
    const float* base = xz + (size_t)(b * LSEQ) * 2 * EINNER + e;
    #pragma unroll
    for (int k = 0; k < 4; k++) {
        int li = l - 3 + k;
        if (li >= 0) acc = fmaf(cw[e*4 + k], base[(size_t)li * 2 * EINNER], acc);
    }
    xi[idx] = acc / (1.0f + __expf(-acc));   // SiLU
}

// ---------------- split-K reduce for x_proj ----------------
__global__ void k_reduce8(const float* __restrict__ part, float* __restrict__ out, int n) {
    int i = blockIdx.x * blockDim.x + threadIdx.x;
    if (i < n) {
        float s = 0.f;
        #pragma unroll
        for (int z = 0; z < 8; z++) s += part[(size_t)z * n + i];
        out[i] = s;
    }
}

// ---------------- scan pass 1: per-chunk local state (h0=0) + chunk decay P ----------------
__global__ void k_scan1(const float* __restrict__ dt, const float* __restrict__ u,
                        const float* __restrict__ dbc, const float* __restrict__ Alog,
                        float* __restrict__ hN, float* __restrict__ P) {
    int e = blockIdx.x * 128 + threadIdx.x;
    int c = blockIdx.y, b = blockIdx.z;
    float A[NSTATE];
    #pragma unroll
    for (int n = 0; n < NSTATE; n++) A[n] = -__expf(Alog[e*NSTATE + n]);
    float h[NSTATE];
    #pragma unroll
    for (int n = 0; n < NSTATE; n++) h[n] = 0.f;
    float dts = 0.f;
    int rowbase = b * LSEQ + c * TCH;
    for (int tt = 0; tt < TCH; tt++) {
        int row = rowbase + tt;
        float d  = dt[(size_t)row * EINNER + e];
        float uu = u [(size_t)row * EINNER + e];
        float du = d * uu;
        const float* bc = dbc + (size_t)row * RBC + RRANK;
        #pragma unroll
        for (int n = 0; n < NSTATE; n++) {
            float a = fexp(d * A[n]);
            h[n] = fmaf(a, h[n], du * bc[n]);
        }
        dts += d;
    }
    int o = ((b * NCHUNK + c) * EINNER + e) * NSTATE;
    #pragma unroll
    for (int n = 0; n < NSTATE; n++) {
        hN[o + n] = h[n];
        P[o + n]  = fexp(dts * A[n]);
    }
}

// ---------------- scan pass 2: sequential chunk combine (tiny) ----------------
__global__ void k_scan2(const float* __restrict__ hN, const float* __restrict__ P,
                        float* __restrict__ S) {
    int idx = blockIdx.x * blockDim.x + threadIdx.x;  // B*E*NSTATE = 32768
    int b = idx >> 14;
    int r = idx & 16383;
    float s = 0.f;
    int base = b * NCHUNK * EINNER * NSTATE + r;
    #pragma unroll
    for (int c = 0; c < NCHUNK; c++) {
        S[base + c * EINNER * NSTATE] = s;
        s = hN[base + c * EINNER * NSTATE] + P[base + c * EINNER * NSTATE] * s;
    }
}

// ---------------- scan pass 3: full scan + y + D skip + silu(z) gate ----------------
__global__ void k_scan3(const float* __restrict__ dt, const float* __restrict__ u,
                        const float* __restrict__ dbc, const float* __restrict__ xz,
                        const float* __restrict__ Alog, const float* __restrict__ Dv,
                        const float* __restrict__ S, float* __restrict__ y) {
    int e = blockIdx.x * 128 + threadIdx.x;
    int c = blockIdx.y, b = blockIdx.z;
    float A[NSTATE];
    #pragma unroll
    for (int n = 0; n < NSTATE; n++) A[n] = -__expf(Alog[e*NSTATE + n]);
    float Dd = Dv[e];
    float h[NSTATE];
    int o = ((b * NCHUNK + c) * EINNER + e) * NSTATE;
    #pragma unroll
    for (int n = 0; n < NSTATE; n++) h[n] = S[o + n];
    int rowbase = b * LSEQ + c * TCH;
    for (int tt = 0; tt < TCH; tt++) {
        int row = rowbase + tt;
        float d  = dt[(size_t)row * EINNER + e];
        float uu = u [(size_t)row * EINNER + e];
        float zz = xz[(size_t)row * 2 * EINNER + EINNER + e];
        float du = d * uu;
        const float* bc = dbc + (size_t)row * RBC + RRANK;
        float acc = 0.f;
        #pragma unroll
        for (int n = 0; n < NSTATE; n++) {
            float a = fexp(d * A[n]);
            h[n] = fmaf(a, h[n], du * bc[n]);
            acc = fmaf(h[n], bc[NSTATE + n], acc);
        }
        acc = fmaf(uu, Dd, acc);
        float sz = zz / (1.0f + fexp(-zz));   // silu(z)
        y[(size_t)row * EINNER + e] = acc * sz;
    }
}

// ---------------- launcher ----------------
extern "C" void kernel_launch(void* const* d_in, const int* in_sizes, int n_in,
                              void* d_out, int out_size) {
    const float* x     = (const float*)d_in[0];
    const float* pos   = (const float*)d_in[1];
    const float* normw = (const float*)d_in[2];
    const float* inw   = (const float*)d_in[3];
    const float* convw = (const float*)d_in[4];
    const float* convb = (const float*)d_in[5];
    const float* xpw   = (const float*)d_in[6];
    const float* dtw   = (const float*)d_in[7];
    const float* dtb   = (const float*)d_in[8];
    const float* alog  = (const float*)d_in[9];
    const float* dvec  = (const float*)d_in[10];
    const float* outw  = (const float*)d_in[11];
    float* out = (float*)d_out;
    (void)in_sizes; (void)n_in; (void)out_size;

    float *ph, *pxn, *pxz, *pxi, *pdbcp, *pdbc, *pdt, *py, *phN, *pP, *pS;
    cudaGetSymbolAddress((void**)&ph,    g_h);
    cudaGetSymbolAddress((void**)&pxn,   g_xn);
    cudaGetSymbolAddress((void**)&pxz,   g_xz);
    cudaGetSymbolAddress((void**)&pxi,   g_xi);
    cudaGetSymbolAddress((void**)&pdbcp, g_dbcp);
    cudaGetSymbolAddress((void**)&pdbc,  g_dbc);
    cudaGetSymbolAddress((void**)&pdt,   g_dt);
    cudaGetSymbolAddress((void**)&py,    g_y);
    cudaGetSymbolAddress((void**)&phN,   g_hN);
    cudaGetSymbolAddress((void**)&pP,    g_P);
    cudaGetSymbolAddress((void**)&pS,    g_S);

    for (int l = 0; l < NLAYERS; l++) {
        const float* hin = (l == 0) ? x : ph;
        // 1. h+pos -> rmsnorm -> xn
        k_addnorm<<<TTOK, 128>>>(hin, pos, normw, pxn);
        // 2. in_proj: (2048x512) x (2048x512)^T -> xz (2048,2048)
        k_mma<128,128,2,4,0><<<dim3(2*EINNER/128, TTOK/128, 1), 256>>>(
            pxn, inw + (size_t)l*2*EINNER*DMODEL, pxz,
            TTOK, 2*EINNER, DMODEL, DMODEL, DMODEL, 2*EINNER, nullptr, 0);
        // 3. depthwise causal conv + SiLU -> xi
        k_conv<<<(TTOK*EINNER)/256, 256>>>(pxz, convw + (size_t)l*EINNER*4,
                                           convb + (size_t)l*EINNER, pxi);
        // 4. x_proj split-K=8 partials + reduce -> dbc (2048,64)
        k_mma<64,64,2,2,0><<<dim3(1, TTOK/64, 8), 128>>>(
            pxi, xpw + (size_t)l*RBC*EINNER, pdbcp,
            TTOK, RBC, EINNER, EINNER, EINNER, RBC, nullptr, TTOK*RBC);
        k_reduce8<<<(TTOK*RBC)/256, 256>>>(pdbcp, pdbc, TTOK*RBC);
        // 5. dt_proj + softplus(+bias) -> dt (2048,1024), K=32
        k_mma<128,128,2,4,1><<<dim3(EINNER/128, TTOK/128, 1), 256>>>(
            pdbc, dtw + (size_t)l*EINNER*RRANK, pdt,
            TTOK, EINNER, RRANK, RBC, RRANK, EINNER, dtb + (size_t)l*EINNER, 0);
        // 6. chunked selective scan (3 passes), fused D skip + silu(z) gate
        k_scan1<<<dim3(EINNER/128, NCHUNK, BATCH), 128>>>(pdt, pxi, pdbc,
                                                          alog + (size_t)l*EINNER*NSTATE,
                                                          phN, pP);
        k_scan2<<<(BATCH*EINNER*NSTATE)/256, 256>>>(phN, pP, pS);
        k_scan3<<<dim3(EINNER/128, NCHUNK, BATCH), 128>>>(pdt, pxi, pdbc, pxz,
                                                          alog + (size_t)l*EINNER*NSTATE,
                                                          dvec + (size_t)l*EINNER, pS, py);
        // 7. out_proj -> next h (or final output)
        float* dest = (l == NLAYERS-1) ? out : ph;
        k_mma<128,64,4,2,0><<<dim3(DMODEL/64, TTOK/128, 1), 256>>>(
            py, outw + (size_t)l*DMODEL*EINNER, dest,
            TTOK, DMODEL, EINNER, EINNER, EINNER, DMODEL, nullptr, 0);
    }
}

// round 3
// speedup vs baseline: 2.4192x; 1.6792x over previous
#include <cuda_runtime.h>
#include <cuda_bf16.h>
#include <math.h>

// ---------------- problem constants ----------------
#define NLAYERS 6
#define BATCH   2
#define LSEQ    1024
#define DMODEL  512
#define EINNER  1024
#define NSTATE  16
#define RRANK   32
#define RBC     64            // RRANK + 2*NSTATE
#define TTOK    (BATCH*LSEQ)  // 2048
#define NCHUNK  32
#define TCH     (LSEQ/NCHUNK) // 32
#define EPSF    1.1920929e-07f

// weight plane layout (bf16 hi/lo), element offsets
#define N_IN   (NLAYERS*2*EINNER*DMODEL)   // 6291456
#define N_XP   (NLAYERS*RBC*EINNER)        // 393216
#define N_DT   (NLAYERS*EINNER*RRANK)      // 196608
#define N_OUT  (NLAYERS*DMODEL*EINNER)     // 3145728
#define OFF_IN  0
#define OFF_XP  (N_IN)
#define OFF_DT  (N_IN+N_XP)
#define OFF_OUT (N_IN+N_XP+N_DT)
#define N_WTOT  (N_IN+N_XP+N_DT+N_OUT)     // 10027008

// ---------------- scratch (device globals; no mallocs allowed) ----------------
__device__ float g_h   [TTOK*DMODEL];
__device__ float g_xz  [TTOK*2*EINNER];
__device__ float g_xi  [TTOK*EINNER];
__device__ float g_dbcp[8*TTOK*RBC];
__device__ float g_dbc [TTOK*RBC];
__device__ float g_dt  [TTOK*EINNER];
__device__ float g_hN  [BATCH*NCHUNK*EINNER*NSTATE];
__device__ float g_P   [BATCH*NCHUNK*EINNER*NSTATE];
__device__ float g_S   [BATCH*NCHUNK*EINNER*NSTATE];
// bf16 hi/lo planes
__device__ __nv_bfloat16 g_wh [N_WTOT], g_wl [N_WTOT];
__device__ __nv_bfloat16 g_xnh[TTOK*DMODEL],  g_xnl[TTOK*DMODEL];
__device__ __nv_bfloat16 g_xih[TTOK*EINNER],  g_xil[TTOK*EINNER];
__device__ __nv_bfloat16 g_dbch[TTOK*RBC],    g_dbcl[TTOK*RBC];
__device__ __nv_bfloat16 g_yh [TTOK*EINNER],  g_yl [TTOK*EINNER];

__device__ __forceinline__ void split_bf16(float v, __nv_bfloat16& h, __nv_bfloat16& l) {
    h = __float2bfloat16(v);
    l = __float2bfloat16(v - __bfloat162float(h));
}

// fast exp2 on FMA pipe, x <= 0 required; clamps at -126 (underflow -> ~0)
__device__ __forceinline__ float fexp2n(float x) {
    x = fmaxf(x, -126.0f);
    float t = x + 12582912.0f;                  // 1.5*2^23
    int   i = __float_as_int(t) - 0x4B400000;
    float r = x - (t - 12582912.0f);            // [-0.5, 0.5]
    float p =          1.3333558e-3f;
    p = fmaf(p, r, 9.6181291e-3f);
    p = fmaf(p, r, 5.5504109e-2f);
    p = fmaf(p, r, 2.4022651e-1f);
    p = fmaf(p, r, 6.9314718e-1f);
    p = fmaf(p, r, 1.0f);
    return __int_as_float(__float_as_int(p) + (i << 23));
}

__device__ __forceinline__ float softplusf(float x) {
    return fmaxf(x, 0.0f) + log1pf(__expf(-fabsf(x)));
}

// ---------------- K0: convert all weights to bf16 hi/lo planes ----------------
__global__ void k_cvtw(const float* __restrict__ inw, const float* __restrict__ xpw,
                       const float* __restrict__ dtw, const float* __restrict__ outw,
                       __nv_bfloat16* __restrict__ wh, __nv_bfloat16* __restrict__ wl) {
    int i4 = blockIdx.x * blockDim.x + threadIdx.x;
    int e0 = i4 * 4;
    if (e0 >= N_WTOT) return;
    const float* src; int off;
    if      (e0 < OFF_XP)  { src = inw;  off = e0 - OFF_IN;  }
    else if (e0 < OFF_DT)  { src = xpw;  off = e0 - OFF_XP;  }
    else if (e0 < OFF_OUT) { src = dtw;  off = e0 - OFF_DT;  }
    else                   { src = outw; off = e0 - OFF_OUT; }
    float4 v = *(const float4*)(src + off);
    __nv_bfloat16 h0,h1,h2,h3,l0,l1,l2,l3;
    split_bf16(v.x,h0,l0); split_bf16(v.y,h1,l1);
    split_bf16(v.z,h2,l2); split_bf16(v.w,h3,l3);
    *(__nv_bfloat162*)&wh[e0]   = __nv_bfloat162(h0,h1);
    *(__nv_bfloat162*)&wh[e0+2] = __nv_bfloat162(h2,h3);
    *(__nv_bfloat162*)&wl[e0]   = __nv_bfloat162(l0,l1);
    *(__nv_bfloat162*)&wl[e0+2] = __nv_bfloat162(l2,l3);
}

// ---------------- K1: h+pos then RMSNorm -> bf16 hi/lo ----------------
__global__ void k_addnorm(const float* __restrict__ hin, const float* __restrict__ pos,
                          const float* __restrict__ nw,
                          __nv_bfloat16* __restrict__ oh, __nv_bfloat16* __restrict__ ol) {
    int t = blockIdx.x;
    int tid = threadIdx.x;        // 128 threads * float4 = 512
    float4 v  = ((const float4*)(hin + t*DMODEL))[tid];
    float4 pv = ((const float4*)(pos + t*DMODEL))[tid];
    v.x += pv.x; v.y += pv.y; v.z += pv.z; v.w += pv.w;
    float ss = v.x*v.x + v.y*v.y + v.z*v.z + v.w*v.w;
    #pragma unroll
    for (int o = 16; o > 0; o >>= 1) ss += __shfl_xor_sync(0xffffffffu, ss, o);
    __shared__ float sred[4];
    if ((tid & 31) == 0) sred[tid >> 5] = ss;
    __syncthreads();
    ss = sred[0] + sred[1] + sred[2] + sred[3];
    float s = rsqrtf(ss * (1.0f/DMODEL) + EPSF);
    float4 w = ((const float4*)nw)[tid];
    float o0 = v.x*s*w.x, o1 = v.y*s*w.y, o2 = v.z*s*w.z, o3 = v.w*s*w.w;
    __nv_bfloat16 h0,h1,h2,h3,l0,l1,l2,l3;
    split_bf16(o0,h0,l0); split_bf16(o1,h1,l1);
    split_bf16(o2,h2,l2); split_bf16(o3,h3,l3);
    int base = t*DMODEL + tid*4;
    *(__nv_bfloat162*)&oh[base]   = __nv_bfloat162(h0,h1);
    *(__nv_bfloat162*)&oh[base+2] = __nv_bfloat162(h2,h3);
    *(__nv_bfloat162*)&ol[base]   = __nv_bfloat162(l0,l1);
    *(__nv_bfloat162*)&ol[base+2] = __nv_bfloat162(l2,l3);
}

// ---------------- bf16-split MMA GEMM (operands pre-split in gmem) ----------------
// C[m,n] = sum_k A[m,k]*W[n,k]; 3-term: ah*bh + ah*bl + al*bh.
// EPI: 0 = plain store, 1 = softplus(acc + bias[n]). grid.z = split-K partials.
__device__ __forceinline__ void mma_bf16(float (&d)[4], const unsigned (&a)[4],
                                         const unsigned (&b)[2]) {
    asm volatile(
        "mma.sync.aligned.m16n8k16.row.col.f32.bf16.bf16.f32 "
        "{%0,%1,%2,%3}, {%4,%5,%6,%7}, {%8,%9}, {%0,%1,%2,%3};\n"
        : "+f"(d[0]), "+f"(d[1]), "+f"(d[2]), "+f"(d[3])
        : "r"(a[0]), "r"(a[1]), "r"(a[2]), "r"(a[3]), "r"(b[0]), "r"(b[1]));
}

template<int BM, int BN, int WARPS_M, int WARPS_N, int EPI>
__global__ void __launch_bounds__(WARPS_M*WARPS_N*32)
k_mma(const __nv_bfloat16* __restrict__ Agh, const __nv_bfloat16* __restrict__ Agl,
      const __nv_bfloat16* __restrict__ Bgh, const __nv_bfloat16* __restrict__ Bgl,
      float* __restrict__ C, int M, int N, int K,
      int lda, int ldw, int ldc,
      const float* __restrict__ bias, int pstride)
{
    constexpr int BK = 32;
    constexpr int THREADS = WARPS_M*WARPS_N*32;
    constexpr int WM = BM/WARPS_M, WN = BN/WARPS_N;
    constexpr int TM = WM/16, TN = WN/8;
    constexpr int LST = BK + 8;                      // bf16 elems per smem row (80B)
    constexpr int LA = BM*(BK/8)/THREADS;            // uint4 loads per plane (A)
    constexpr int LB = BN*(BK/8)/THREADS;

    __shared__ __align__(16) __nv_bfloat16 Ah[BM*LST], Al[BM*LST];
    __shared__ __align__(16) __nv_bfloat16 Bh[BN*LST], Bl[BN*LST];

    const int tid  = threadIdx.x;
    const int lane = tid & 31;
    const int warp = tid >> 5;
    const int wm = (warp / WARPS_N) * WM;
    const int wn = (warp % WARPS_N) * WN;
    const int m0 = blockIdx.y * BM, n0 = blockIdx.x * BN;
    const int kLen = K / gridDim.z;
    const int k0 = blockIdx.z * kLen;
    const int niter = kLen / BK;

    float acc[TM][TN][4];
    #pragma unroll
    for (int i = 0; i < TM; i++)
        #pragma unroll
        for (int j = 0; j < TN; j++)
            #pragma unroll
            for (int q = 0; q < 4; q++) acc[i][j][q] = 0.0f;

    uint4 sAh[LA], sAl[LA], sBh[LB], sBl[LB];

    // prologue: load tile 0 (uint4 = 8 bf16)
    #pragma unroll
    for (int i = 0; i < LA; i++) {
        int c = tid + i*THREADS; int r = c >> 2, kc = c & 3;
        size_t g = (size_t)(m0 + r) * lda + k0 + kc*8;
        sAh[i] = *(const uint4*)&Agh[g];
        sAl[i] = *(const uint4*)&Agl[g];
    }
    #pragma unroll
    for (int i = 0; i < LB; i++) {
        int c = tid + i*THREADS; int r = c >> 2, kc = c & 3;
        size_t g = (size_t)(n0 + r) * ldw + k0 + kc*8;
        sBh[i] = *(const uint4*)&Bgh[g];
        sBl[i] = *(const uint4*)&Bgl[g];
    }

    for (int kt = 0; kt < niter; kt++) {
        __syncthreads();
        #pragma unroll
        for (int i = 0; i < LA; i++) {
            int c = tid + i*THREADS; int r = c >> 2, kc = c & 3;
            int off = r*LST + kc*8;
            *(uint4*)&Ah[off] = sAh[i];
            *(uint4*)&Al[off] = sAl[i];
        }
        #pragma unroll
        for (int i = 0; i < LB; i++) {
            int c = tid + i*THREADS; int r = c >> 2, kc = c & 3;
            int off = r*LST + kc*8;
            *(uint4*)&Bh[off] = sBh[i];
            *(uint4*)&Bl[off] = sBl[i];
        }
        __syncthreads();

        if (kt + 1 < niter) {
            int kb = k0 + (kt+1)*BK;
            #pragma unroll
            for (int i = 0; i < LA; i++) {
                int c = tid + i*THREADS; int r = c >> 2, kc = c & 3;
                size_t g = (size_t)(m0 + r) * lda + kb + kc*8;
                sAh[i] = *(const uint4*)&Agh[g];
                sAl[i] = *(const uint4*)&Agl[g];
            }
            #pragma unroll
            for (int i = 0; i < LB; i++) {
                int c = tid + i*THREADS; int r = c >> 2, kc = c & 3;
                size_t g = (size_t)(n0 + r) * ldw + kb + kc*8;
                sBh[i] = *(const uint4*)&Bgh[g];
                sBl[i] = *(const uint4*)&Bgl[g];
            }
        }

        #pragma unroll
        for (int s = 0; s < 2; s++) {
            const int kb = s*16 + (lane & 3)*2;
            unsigned bh[TN][2], bl[TN][2];
            #pragma unroll
            for (int j = 0; j < TN; j++) {
                int nb = (wn + j*8 + (lane >> 2)) * LST;
                bh[j][0] = *(const unsigned*)&Bh[nb + kb];
                bh[j][1] = *(const unsigned*)&Bh[nb + kb + 8];
                bl[j][0] = *(const unsigned*)&Bl[nb + kb];
                bl[j][1] = *(const unsigned*)&Bl[nb + kb + 8];
            }
            #pragma unroll
            for (int i = 0; i < TM; i++) {
                int mb = (wm + i*16 + (lane >> 2)) * LST;
                unsigned ah[4], al[4];
                ah[0] = *(const unsigned*)&Ah[mb + kb];
                ah[1] = *(const unsigned*)&Ah[mb + 8*LST + kb];
                ah[2] = *(const unsigned*)&Ah[mb + kb + 8];
                ah[3] = *(const unsigned*)&Ah[mb + 8*LST + kb + 8];
                al[0] = *(const unsigned*)&Al[mb + kb];
                al[1] = *(const unsigned*)&Al[mb + 8*LST + kb];
                al[2] = *(const unsigned*)&Al[mb + kb + 8];
                al[3] = *(const unsigned*)&Al[mb + 8*LST + kb + 8];
                #pragma unroll
                for (int j = 0; j < TN; j++) {
                    mma_bf16(acc[i][j], ah, bh[j]);
                    mma_bf16(acc[i][j], ah, bl[j]);
                    mma_bf16(acc[i][j], al, bh[j]);
                }
            }
        }
    }

    float* Cp = C + (size_t)blockIdx.z * pstride;
    #pragma unroll
    for (int i = 0; i < TM; i++) {
        int row = m0 + wm + i*16 + (lane >> 2);
        #pragma unroll
        for (int j = 0; j < TN; j++) {
            int col = n0 + wn + j*8 + (lane & 3)*2;
            float2 v0, v1;
            if (EPI == 1) {
                float b0 = bias[col], b1 = bias[col+1];
                v0.x = softplusf(acc[i][j][0] + b0);
                v0.y = softplusf(acc[i][j][1] + b1);
                v1.x = softplusf(acc[i][j][2] + b0);
                v1.y = softplusf(acc[i][j][3] + b1);
            } else {
                v0.x = acc[i][j][0]; v0.y = acc[i][j][1];
                v1.x = acc[i][j][2]; v1.y = acc[i][j][3];
            }
            *(float2*)&Cp[(size_t)row * ldc + col]     = v0;
            *(float2*)&Cp[(size_t)(row+8) * ldc + col] = v1;
        }
    }
}

// ---------------- K3: causal depthwise conv (k=4) + bias + SiLU ----------------
__global__ void k_conv(const float* __restrict__ xz, const float* __restrict__ cw,
                       const float* __restrict__ cb, float* __restrict__ xi,
                       __nv_bfloat16* __restrict__ xih, __nv_bfloat16* __restrict__ xil) {
    int idx = blockIdx.x * blockDim.x + threadIdx.x;   // over B*L*E
    int e = idx & (EINNER - 1);
    int l = (idx >> 10) & (LSEQ - 1);
    int b = idx >> 20;
    float acc = cb[e];
    const float* base = xz + (size_t)(b * LSEQ) * 2 * EINNER + e;
    #pragma unroll
    for (int k = 0; k < 4; k++) {
        int li = l - 3 + k;
        if (li >= 0) acc = fmaf(cw[e*4 + k], base[(size_t)li * 2 * EINNER], acc);
    }
    float v = acc / (1.0f + __expf(-acc));   // SiLU
    xi[idx] = v;
    __nv_bfloat16 h, lo; split_bf16(v, h, lo);
    xih[idx] = h; xil[idx] = lo;
}

// ---------------- split-K reduce for x_proj (+ bf16 planes) ----------------
__global__ void k_reduce8(const float* __restrict__ part, float* __restrict__ out,
                          __nv_bfloat16* __restrict__ oh, __nv_bfloat16* __restrict__ ol,
                          int n) {
    int i = blockIdx.x * blockDim.x + threadIdx.x;
    if (i < n) {
        float s = 0.f;
        #pragma unroll
        for (int z = 0; z < 8; z++) s += part[(size_t)z * n + i];
        out[i] = s;
        __nv_bfloat16 h, lo; split_bf16(s, h, lo);
        oh[i] = h; ol[i] = lo;
    }
}

// ---------------- scan pass 1: per-chunk local state (h0=0) + chunk decay P ----------------
__global__ void k_scan1(const float* __restrict__ dt, const float* __restrict__ u,
                        const float* __restrict__ dbc, const float* __restrict__ Alog,
                        float* __restrict__ hN, float* __restrict__ P) {
    int e = blockIdx.x * 128 + threadIdx.x;
    int c = blockIdx.y, b = blockIdx.z;
    float A2[NSTATE];
    #pragma unroll
    for (int n = 0; n < NSTATE; n++)
        A2[n] = -__expf(Alog[e*NSTATE + n]) * 1.4426950408889634f;
    float h[NSTATE];
    #pragma unroll
    for (int n = 0; n < NSTATE; n++) h[n] = 0.f;
    float dts = 0.f;
    int rowbase = b * LSEQ + c * TCH;
    for (int tt = 0; tt < TCH; tt++) {
        int row = rowbase + tt;
        float d  = dt[(size_t)row * EINNER + e];
        float uu = u [(size_t)row * EINNER + e];
        float du = d * uu;
        const float* bc = dbc + (size_t)row * RBC + RRANK;
        #pragma unroll
        for (int n = 0; n < NSTATE; n++) {
            float a = fexp2n(d * A2[n]);
            h[n] = fmaf(a, h[n], du * bc[n]);
        }
        dts += d;
    }
    int o = ((b * NCHUNK + c) * EINNER + e) * NSTATE;
    #pragma unroll
    for (int n = 0; n < NSTATE; n++) {
        hN[o + n] = h[n];
        P[o + n]  = fexp2n(dts * A2[n]);
    }
}

// ---------------- scan pass 2: sequential chunk combine (tiny) ----------------
__global__ void k_scan2(const float* __restrict__ hN, const float* __restrict__ P,
                        float* __restrict__ S) {
    int idx = blockIdx.x * blockDim.x + threadIdx.x;  // B*E*NSTATE = 32768
    int b = idx >> 14;
    int r = idx & 16383;
    float s = 0.f;
    int base = b * NCHUNK * EINNER * NSTATE + r;
    #pragma unroll
    for (int c = 0; c < NCHUNK; c++) {
        S[base + c * EINNER * NSTATE] = s;
        s = hN[base + c * EINNER * NSTATE] + P[base + c * EINNER * NSTATE] * s;
    }
}

// ---------------- scan pass 3: full scan + y + D skip + silu(z) gate -> bf16 planes ----
__global__ void k_scan3(const float* __restrict__ dt, const float* __restrict__ u,
                        const float* __restrict__ dbc, const float* __restrict__ xz,
                        const float* __restrict__ Alog, const float* __restrict__ Dv,
                        const float* __restrict__ S,
                        __nv_bfloat16* __restrict__ yh, __nv_bfloat16* __restrict__ yl) {
    int e = blockIdx.x * 128 + threadIdx.x;
    int c = blockIdx.y, b = blockIdx.z;
    float A2[NSTATE];
    #pragma unroll
    for (int n = 0; n < NSTATE; n++)
        A2[n] = -__expf(Alog[e*NSTATE + n]) * 1.4426950408889634f;
    float Dd = Dv[e];
    float h[NSTATE];
    int o = ((b * NCHUNK + c) * EINNER + e) * NSTATE;
    #pragma unroll
    for (int n = 0; n < NSTATE; n++) h[n] = S[o + n];
    int rowbase = b * LSEQ + c * TCH;
    for (int tt = 0; tt < TCH; tt++) {
        int row = rowbase + tt;
        float d  = dt[(size_t)row * EINNER + e];
        float uu = u [(size_t)row * EINNER + e];
        float zz = xz[(size_t)row * 2 * EINNER + EINNER + e];
        float du = d * uu;
        const float* bc = dbc + (size_t)row * RBC + RRANK;
        float acc = 0.f;
        #pragma unroll
        for (int n = 0; n < NSTATE; n++) {
            float a = fexp2n(d * A2[n]);
            h[n] = fmaf(a, h[n], du * bc[n]);
            acc = fmaf(h[n], bc[NSTATE + n], acc);
        }
        acc = fmaf(uu, Dd, acc);
        float sz = zz / (1.0f + __expf(-zz));   // silu(z)
        float yv = acc * sz;
        __nv_bfloat16 hh, ll; split_bf16(yv, hh, ll);
        size_t oi = (size_t)row * EINNER + e;
        yh[oi] = hh; yl[oi] = ll;
    }
}

// ---------------- final out_proj epilogue target is fp32 ----------------

extern "C" void kernel_launch(void* const* d_in, const int* in_sizes, int n_in,
                              void* d_out, int out_size) {
    const float* x     = (const float*)d_in[0];
    const float* pos   = (const float*)d_in[1];
    const float* normw = (const float*)d_in[2];
    const float* inw   = (const float*)d_in[3];
    const float* convw = (const float*)d_in[4];
    const float* convb = (const float*)d_in[5];
    const float* xpw   = (const float*)d_in[6];
    const float* dtw   = (const float*)d_in[7];
    const float* dtb   = (const float*)d_in[8];
    const float* alog  = (const float*)d_in[9];
    const float* dvec  = (const float*)d_in[10];
    const float* outw  = (const float*)d_in[11];
    float* out = (float*)d_out;
    (void)in_sizes; (void)n_in; (void)out_size;

    float *ph, *pxz, *pxi, *pdbcp, *pdbc, *pdt, *phN, *pP, *pS;
    __nv_bfloat16 *pwh, *pwl, *pxnh, *pxnl, *pxih, *pxil, *pdbch, *pdbcl, *pyh, *pyl;
    cudaGetSymbolAddress((void**)&ph,    g_h);
    cudaGetSymbolAddress((void**)&pxz,   g_xz);
    cudaGetSymbolAddress((void**)&pxi,   g_xi);
    cudaGetSymbolAddress((void**)&pdbcp, g_dbcp);
    cudaGetSymbolAddress((void**)&pdbc,  g_dbc);
    cudaGetSymbolAddress((void**)&pdt,   g_dt);
    cudaGetSymbolAddress((void**)&phN,   g_hN);
    cudaGetSymbolAddress((void**)&pP,    g_P);
    cudaGetSymbolAddress((void**)&pS,    g_S);
    cudaGetSymbolAddress((void**)&pwh,   g_wh);
    cudaGetSymbolAddress((void**)&pwl,   g_wl);
    cudaGetSymbolAddress((void**)&pxnh,  g_xnh);
    cudaGetSymbolAddress((void**)&pxnl,  g_xnl);
    cudaGetSymbolAddress((void**)&pxih,  g_xih);
    cudaGetSymbolAddress((void**)&pxil,  g_xil);
    cudaGetSymbolAddress((void**)&pdbch, g_dbch);
    cudaGetSymbolAddress((void**)&pdbcl, g_dbcl);
    cudaGetSymbolAddress((void**)&pyh,   g_yh);
    cudaGetSymbolAddress((void**)&pyl,   g_yl);

    // one-shot weight conversion (runs each call; deterministic)
    k_cvtw<<<(N_WTOT/4 + 255)/256, 256>>>(inw, xpw, dtw, outw, pwh, pwl);

    for (int l = 0; l < NLAYERS; l++) {
        const float* hin = (l == 0) ? x : ph;
        // 1. h+pos -> rmsnorm -> xn planes
        k_addnorm<<<TTOK, 128>>>(hin, pos, normw, pxnh, pxnl);
        // 2. in_proj -> xz fp32 (2048,2048)
        k_mma<128,128,2,4,0><<<dim3(2*EINNER/128, TTOK/128, 1), 256>>>(
            pxnh, pxnl, pwh + OFF_IN + (size_t)l*2*EINNER*DMODEL,
            pwl + OFF_IN + (size_t)l*2*EINNER*DMODEL, pxz,
            TTOK, 2*EINNER, DMODEL, DMODEL, DMODEL, 2*EINNER, nullptr, 0);
        // 3. conv + SiLU -> xi fp32 + planes
        k_conv<<<(TTOK*EINNER)/256, 256>>>(pxz, convw + (size_t)l*EINNER*4,
                                           convb + (size_t)l*EINNER, pxi, pxih, pxil);
        // 4. x_proj split-K=8 + reduce -> dbc fp32 + planes
        k_mma<64,64,2,2,0><<<dim3(1, TTOK/64, 8), 128>>>(
            pxih, pxil, pwh + OFF_XP + (size_t)l*RBC*EINNER,
            pwl + OFF_XP + (size_t)l*RBC*EINNER, pdbcp,
            TTOK, RBC, EINNER, EINNER, EINNER, RBC, nullptr, TTOK*RBC);
        k_reduce8<<<(TTOK*RBC)/256, 256>>>(pdbcp, pdbc, pdbch, pdbcl, TTOK*RBC);
        // 5. dt_proj + softplus(+bias) -> dt fp32
        k_mma<128,128,2,4,1><<<dim3(EINNER/128, TTOK/128, 1), 256>>>(
            pdbch, pdbcl, pwh + OFF_DT + (size_t)l*EINNER*RRANK,
            pwl + OFF_DT + (size_t)l*EINNER*RRANK, pdt,
            TTOK, EINNER, RRANK, RBC, RRANK, EINNER, dtb + (size_t)l*EINNER, 0);
        // 6. chunked selective scan (32 chunks), fused D skip + silu(z) gate
        k_scan1<<<dim3(EINNER/128, NCHUNK, BATCH), 128>>>(pdt, pxi, pdbc,
                                                          alog + (size_t)l*EINNER*NSTATE,
                                                          phN, pP);
        k_scan2<<<(BATCH*EINNER*NSTATE)/256, 256>>>(phN, pP, pS);
        k_scan3<<<dim3(EINNER/128, NCHUNK, BATCH), 128>>>(pdt, pxi, pdbc, pxz,
                                                          alog + (size_t)l*EINNER*NSTATE,
                                                          dvec + (size_t)l*EINNER, pS,
                                                          pyh, pyl);
        // 7. out_proj -> next h (or final output)
        float* dest = (l == NLAYERS-1) ? out : ph;
        k_mma<128,64,4,2,0><<<dim3(DMODEL/64, TTOK/128, 1), 256>>>(
            pyh, pyl, pwh + OFF_OUT + (size_t)l*DMODEL*EINNER,
            pwl + OFF_OUT + (size_t)l*DMODEL*EINNER, dest,
            TTOK, DMODEL, EINNER, EINNER, EINNER, DMODEL, nullptr, 0);
    }
}

// round 4
// speedup vs baseline: 2.7391x; 1.1323x over previous
#include <cuda_runtime.h>
#include <cuda_bf16.h>
#include <math.h>

// ---------------- problem constants ----------------
#define NLAYERS 6
#define BATCH   2
#define LSEQ    1024
#define DMODEL  512
#define EINNER  1024
#define NSTATE  16
#define RRANK   32
#define RBC     64            // RRANK + 2*NSTATE
#define TTOK    (BATCH*LSEQ)  // 2048
#define NCHUNK  32
#define TCH     (LSEQ/NCHUNK) // 32
#define EPSF    1.1920929e-07f
#define L2E     1.4426950408889634f

// weight plane layout (bf16 hi/lo), element offsets
#define N_IN   (NLAYERS*2*EINNER*DMODEL)
#define N_XP   (NLAYERS*RBC*EINNER)
#define N_DT   (NLAYERS*EINNER*RRANK)
#define N_OUT  (NLAYERS*DMODEL*EINNER)
#define OFF_IN  0
#define OFF_XP  (N_IN)
#define OFF_DT  (N_IN+N_XP)
#define OFF_OUT (N_IN+N_XP+N_DT)
#define N_WTOT  (N_IN+N_XP+N_DT+N_OUT)

// ---------------- scratch ----------------
__device__ float g_h   [TTOK*DMODEL];
__device__ float g_xz  [TTOK*2*EINNER];
__device__ float g_xi  [TTOK*EINNER];
__device__ float g_dbcp[8*TTOK*RBC];
__device__ float g_dbc [TTOK*RBC];
__device__ float g_dt  [TTOK*EINNER];
__device__ float g_hN  [BATCH*NCHUNK*EINNER*NSTATE];
__device__ float g_P   [BATCH*NCHUNK*EINNER*NSTATE];
__device__ float g_S   [BATCH*NCHUNK*EINNER*NSTATE];
__device__ __nv_bfloat16 g_wh [N_WTOT], g_wl [N_WTOT];
__device__ __nv_bfloat16 g_xnh[TTOK*DMODEL],  g_xnl[TTOK*DMODEL];
__device__ __nv_bfloat16 g_xih[TTOK*EINNER],  g_xil[TTOK*EINNER];
__device__ __nv_bfloat16 g_dbch[TTOK*RBC],    g_dbcl[TTOK*RBC];
__device__ __nv_bfloat16 g_yh [TTOK*EINNER],  g_yl [TTOK*EINNER];

__device__ __forceinline__ void split_bf16(float v, __nv_bfloat16& h, __nv_bfloat16& l) {
    h = __float2bfloat16(v);
    l = __float2bfloat16(v - __bfloat162float(h));
}

// fast exp2 on FMA pipe, x <= 0; clamps at -126
__device__ __forceinline__ float fexp2n(float x) {
    x = fmaxf(x, -126.0f);
    float t = x + 12582912.0f;
    int   i = __float_as_int(t) - 0x4B400000;
    float r = x - (t - 12582912.0f);
    float p =          1.3333558e-3f;
    p = fmaf(p, r, 9.6181291e-3f);
    p = fmaf(p, r, 5.5504109e-2f);
    p = fmaf(p, r, 2.4022651e-1f);
    p = fmaf(p, r, 6.9314718e-1f);
    p = fmaf(p, r, 1.0f);
    return __int_as_float(__float_as_int(p) + (i << 23));
}

__device__ __forceinline__ float softplusf(float x) {
    return fmaxf(x, 0.0f) + log1pf(__expf(-fabsf(x)));
}

// ---------------- K0: weights -> bf16 hi/lo planes ----------------
__global__ void k_cvtw(const float* __restrict__ inw, const float* __restrict__ xpw,
                       const float* __restrict__ dtw, const float* __restrict__ outw,
                       __nv_bfloat16* __restrict__ wh, __nv_bfloat16* __restrict__ wl) {
    int i4 = blockIdx.x * blockDim.x + threadIdx.x;
    int e0 = i4 * 4;
    if (e0 >= N_WTOT) return;
    const float* src; int off;
    if      (e0 < OFF_XP)  { src = inw;  off = e0 - OFF_IN;  }
    else if (e0 < OFF_DT)  { src = xpw;  off = e0 - OFF_XP;  }
    else if (e0 < OFF_OUT) { src = dtw;  off = e0 - OFF_DT;  }
    else                   { src = outw; off = e0 - OFF_OUT; }
    float4 v = *(const float4*)(src + off);
    __nv_bfloat16 h0,h1,h2,h3,l0,l1,l2,l3;
    split_bf16(v.x,h0,l0); split_bf16(v.y,h1,l1);
    split_bf16(v.z,h2,l2); split_bf16(v.w,h3,l3);
    *(__nv_bfloat162*)&wh[e0]   = __nv_bfloat162(h0,h1);
    *(__nv_bfloat162*)&wh[e0+2] = __nv_bfloat162(h2,h3);
    *(__nv_bfloat162*)&wl[e0]   = __nv_bfloat162(l0,l1);
    *(__nv_bfloat162*)&wl[e0+2] = __nv_bfloat162(l2,l3);
}

// ---------------- K1: h+pos then RMSNorm -> bf16 hi/lo ----------------
__global__ void k_addnorm(const float* __restrict__ hin, const float* __restrict__ pos,
                          const float* __restrict__ nw,
                          __nv_bfloat16* __restrict__ oh, __nv_bfloat16* __restrict__ ol) {
    int t = blockIdx.x;
    int tid = threadIdx.x;        // 128 threads * float4 = 512
    float4 v  = ((const float4*)(hin + t*DMODEL))[tid];
    float4 pv = ((const float4*)(pos + t*DMODEL))[tid];
    v.x += pv.x; v.y += pv.y; v.z += pv.z; v.w += pv.w;
    float ss = v.x*v.x + v.y*v.y + v.z*v.z + v.w*v.w;
    #pragma unroll
    for (int o = 16; o > 0; o >>= 1) ss += __shfl_xor_sync(0xffffffffu, ss, o);
    __shared__ float sred[4];
    if ((tid & 31) == 0) sred[tid >> 5] = ss;
    __syncthreads();
    ss = sred[0] + sred[1] + sred[2] + sred[3];
    float s = rsqrtf(ss * (1.0f/DMODEL) + EPSF);
    float4 w = ((const float4*)nw)[tid];
    float o0 = v.x*s*w.x, o1 = v.y*s*w.y, o2 = v.z*s*w.z, o3 = v.w*s*w.w;
    __nv_bfloat16 h0,h1,h2,h3,l0,l1,l2,l3;
    split_bf16(o0,h0,l0); split_bf16(o1,h1,l1);
    split_bf16(o2,h2,l2); split_bf16(o3,h3,l3);
    int base = t*DMODEL + tid*4;
    *(__nv_bfloat162*)&oh[base]   = __nv_bfloat162(h0,h1);
    *(__nv_bfloat162*)&oh[base+2] = __nv_bfloat162(h2,h3);
    *(__nv_bfloat162*)&ol[base]   = __nv_bfloat162(l0,l1);
    *(__nv_bfloat162*)&ol[base+2] = __nv_bfloat162(l2,l3);
}

// ---------------- bf16-split MMA GEMM, double-buffered smem ----------------
__device__ __forceinline__ void mma_bf16(float (&d)[4], const unsigned (&a)[4],
                                         const unsigned (&b)[2]) {
    asm volatile(
        "mma.sync.aligned.m16n8k16.row.col.f32.bf16.bf16.f32 "
        "{%0,%1,%2,%3}, {%4,%5,%6,%7}, {%8,%9}, {%0,%1,%2,%3};\n"
        : "+f"(d[0]), "+f"(d[1]), "+f"(d[2]), "+f"(d[3])
        : "r"(a[0]), "r"(a[1]), "r"(a[2]), "r"(a[3]), "r"(b[0]), "r"(b[1]));
}

// BM=BN=64, 4 warps (128 thr), BK=32, 3-term bf16-split, double buffer.
template<int EPI>
__global__ void __launch_bounds__(128)
k_mma(const __nv_bfloat16* __restrict__ Agh, const __nv_bfloat16* __restrict__ Agl,
      const __nv_bfloat16* __restrict__ Bgh, const __nv_bfloat16* __restrict__ Bgl,
      float* __restrict__ C, int K, int lda, int ldw, int ldc,
      const float* __restrict__ bias, int pstride)
{
    constexpr int BM = 64, BN = 64, BK = 32, THREADS = 128;
    constexpr int TM = 2, TN = 4;               // WM=32, WN=32
    constexpr int LST = BK + 8;                 // 40 bf16 per smem row
    constexpr int LA = BM*(BK/8)/THREADS;       // uint4 per plane = 2
    constexpr int LB = BN*(BK/8)/THREADS;       // 2

    __shared__ __align__(16) __nv_bfloat16 Ah[2][BM*LST], Al[2][BM*LST];
    __shared__ __align__(16) __nv_bfloat16 Bh[2][BN*LST], Bl[2][BN*LST];

    const int tid  = threadIdx.x;
    const int lane = tid & 31;
    const int warp = tid >> 5;
    const int wm = (warp >> 1) * 32;
    const int wn = (warp & 1) * 32;
    const int m0 = blockIdx.y * BM, n0 = blockIdx.x * BN;
    const int kLen = K / gridDim.z;
    const int k0 = blockIdx.z * kLen;
    const int niter = kLen / BK;

    float acc[TM][TN][4];
    #pragma unroll
    for (int i = 0; i < TM; i++)
        #pragma unroll
        for (int j = 0; j < TN; j++)
            #pragma unroll
            for (int q = 0; q < 4; q++) acc[i][j][q] = 0.0f;

    uint4 sAh[LA], sAl[LA], sBh[LB], sBl[LB];
    const int r_  = (tid + 0*THREADS) >> 2, kc_ = (tid + 0*THREADS) & 3;
    const int r2_ = (tid + 1*THREADS) >> 2, kc2_ = (tid + 1*THREADS) & 3;

    // prologue: tile 0 -> regs -> smem buf 0
    {
        size_t gA0 = (size_t)(m0 + r_ ) * lda + k0 + kc_ *8;
        size_t gA1 = (size_t)(m0 + r2_) * lda + k0 + kc2_*8;
        size_t gB0 = (size_t)(n0 + r_ ) * ldw + k0 + kc_ *8;
        size_t gB1 = (size_t)(n0 + r2_) * ldw + k0 + kc2_*8;
        sAh[0] = *(const uint4*)&Agh[gA0]; sAl[0] = *(const uint4*)&Agl[gA0];
        sAh[1] = *(const uint4*)&Agh[gA1]; sAl[1] = *(const uint4*)&Agl[gA1];
        sBh[0] = *(const uint4*)&Bgh[gB0]; sBl[0] = *(const uint4*)&Bgl[gB0];
        sBh[1] = *(const uint4*)&Bgh[gB1]; sBl[1] = *(const uint4*)&Bgl[gB1];
        int o0 = r_*LST + kc_*8, o1 = r2_*LST + kc2_*8;
        *(uint4*)&Ah[0][o0] = sAh[0]; *(uint4*)&Al[0][o0] = sAl[0];
        *(uint4*)&Ah[0][o1] = sAh[1]; *(uint4*)&Al[0][o1] = sAl[1];
        *(uint4*)&Bh[0][o0] = sBh[0]; *(uint4*)&Bl[0][o0] = sBl[0];
        *(uint4*)&Bh[0][o1] = sBh[1]; *(uint4*)&Bl[0][o1] = sBl[1];
    }
    __syncthreads();

    for (int kt = 0; kt < niter; kt++) {
        const int cur = kt & 1;
        const bool more = (kt + 1 < niter);
        if (more) {
            int kb = k0 + (kt+1)*BK;
            size_t gA0 = (size_t)(m0 + r_ ) * lda + kb + kc_ *8;
            size_t gA1 = (size_t)(m0 + r2_) * lda + kb + kc2_*8;
            size_t gB0 = (size_t)(n0 + r_ ) * ldw + kb + kc_ *8;
            size_t gB1 = (size_t)(n0 + r2_) * ldw + kb + kc2_*8;
            sAh[0] = *(const uint4*)&Agh[gA0]; sAl[0] = *(const uint4*)&Agl[gA0];
            sAh[1] = *(const uint4*)&Agh[gA1]; sAl[1] = *(const uint4*)&Agl[gA1];
            sBh[0] = *(const uint4*)&Bgh[gB0]; sBl[0] = *(const uint4*)&Bgl[gB0];
            sBh[1] = *(const uint4*)&Bgh[gB1]; sBl[1] = *(const uint4*)&Bgl[gB1];
        }

        #pragma unroll
        for (int s = 0; s < 2; s++) {
            const int kb = s*16 + (lane & 3)*2;
            unsigned bhf[TN][2], blf[TN][2];
            #pragma unroll
            for (int j = 0; j < TN; j++) {
                int nb = (wn + j*8 + (lane >> 2)) * LST;
                bhf[j][0] = *(const unsigned*)&Bh[cur][nb + kb];
                bhf[j][1] = *(const unsigned*)&Bh[cur][nb + kb + 8];
                blf[j][0] = *(const unsigned*)&Bl[cur][nb + kb];
                blf[j][1] = *(const unsigned*)&Bl[cur][nb + kb + 8];
            }
            #pragma unroll
            for (int i = 0; i < TM; i++) {
                int mb = (wm + i*16 + (lane >> 2)) * LST;
                unsigned ahf[4], alf[4];
                ahf[0] = *(const unsigned*)&Ah[cur][mb + kb];
                ahf[1] = *(const unsigned*)&Ah[cur][mb + 8*LST + kb];
                ahf[2] = *(const unsigned*)&Ah[cur][mb + kb + 8];
                ahf[3] = *(const unsigned*)&Ah[cur][mb + 8*LST + kb + 8];
                alf[0] = *(const unsigned*)&Al[cur][mb + kb];
                alf[1] = *(const unsigned*)&Al[cur][mb + 8*LST + kb];
                alf[2] = *(const unsigned*)&Al[cur][mb + kb + 8];
                alf[3] = *(const unsigned*)&Al[cur][mb + 8*LST + kb + 8];
                #pragma unroll
                for (int j = 0; j < TN; j++) {
                    mma_bf16(acc[i][j], ahf, bhf[j]);
                    mma_bf16(acc[i][j], ahf, blf[j]);
                    mma_bf16(acc[i][j], alf, bhf[j]);
                }
            }
        }

        if (more) {
            int nxt = cur ^ 1;
            int o0 = r_*LST + kc_*8, o1 = r2_*LST + kc2_*8;
            *(uint4*)&Ah[nxt][o0] = sAh[0]; *(uint4*)&Al[nxt][o0] = sAl[0];
            *(uint4*)&Ah[nxt][o1] = sAh[1]; *(uint4*)&Al[nxt][o1] = sAl[1];
            *(uint4*)&Bh[nxt][o0] = sBh[0]; *(uint4*)&Bl[nxt][o0] = sBl[0];
            *(uint4*)&Bh[nxt][o1] = sBh[1]; *(uint4*)&Bl[nxt][o1] = sBl[1];
        }
        __syncthreads();
    }

    float* Cp = C + (size_t)blockIdx.z * pstride;
    #pragma unroll
    for (int i = 0; i < TM; i++) {
        int row = m0 + wm + i*16 + (lane >> 2);
        #pragma unroll
        for (int j = 0; j < TN; j++) {
            int col = n0 + wn + j*8 + (lane & 3)*2;
            float2 v0, v1;
            if (EPI == 1) {
                float b0 = bias[col], b1 = bias[col+1];
                v0.x = softplusf(acc[i][j][0] + b0);
                v0.y = softplusf(acc[i][j][1] + b1);
                v1.x = softplusf(acc[i][j][2] + b0);
                v1.y = softplusf(acc[i][j][3] + b1);
            } else {
                v0.x = acc[i][j][0]; v0.y = acc[i][j][1];
                v1.x = acc[i][j][2]; v1.y = acc[i][j][3];
            }
            *(float2*)&Cp[(size_t)row * ldc + col]     = v0;
            *(float2*)&Cp[(size_t)(row+8) * ldc + col] = v1;
        }
    }
}

// ---------------- K3: causal depthwise conv (k=4) + bias + SiLU, 4 tokens/thread ----
__global__ void k_conv(const float* __restrict__ xz, const float* __restrict__ cw,
                       const float* __restrict__ cb, float* __restrict__ xi,
                       __nv_bfloat16* __restrict__ xih, __nv_bfloat16* __restrict__ xil) {
    int idx = blockIdx.x * blockDim.x + threadIdx.x;   // over B*(L/4)*E
    int e  = idx & (EINNER - 1);
    int lg = (idx >> 10) & (LSEQ/4 - 1);
    int b  = idx >> 18;
    int l0 = lg * 4;
    const float* base = xz + (size_t)(b * LSEQ) * 2 * EINNER + e;
    float xv[7];
    #pragma unroll
    for (int j = 0; j < 7; j++) {
        int li = l0 - 3 + j;
        xv[j] = (li >= 0) ? base[(size_t)li * 2 * EINNER] : 0.0f;
    }
    float w0 = cw[e*4+0], w1 = cw[e*4+1], w2 = cw[e*4+2], w3 = cw[e*4+3];
    float bb = cb[e];
    #pragma unroll
    for (int t = 0; t < 4; t++) {
        float acc = bb;
        acc = fmaf(w0, xv[t+0], acc);
        acc = fmaf(w1, xv[t+1], acc);
        acc = fmaf(w2, xv[t+2], acc);
        acc = fmaf(w3, xv[t+3], acc);
        float v = acc / (1.0f + __expf(-acc));
        size_t oi = (size_t)(b*LSEQ + l0 + t) * EINNER + e;
        xi[oi] = v;
        __nv_bfloat16 h, lo; split_bf16(v, h, lo);
        xih[oi] = h; xil[oi] = lo;
    }
}

// ---------------- split-K reduce for x_proj (+ bf16 planes) ----------------
__global__ void k_reduce8(const float* __restrict__ part, float* __restrict__ out,
                          __nv_bfloat16* __restrict__ oh, __nv_bfloat16* __restrict__ ol,
                          int n) {
    int i = blockIdx.x * blockDim.x + threadIdx.x;
    if (i < n) {
        float s = 0.f;
        #pragma unroll
        for (int z = 0; z < 8; z++) s += part[(size_t)z * n + i];
        out[i] = s;
        __nv_bfloat16 h, lo; split_bf16(s, h, lo);
        oh[i] = h; ol[i] = lo;
    }
}

// ---------------- A setup helper: detect A[n] = (n+1)*A[0] structure --------------
__device__ __forceinline__ bool load_A(const float* __restrict__ Alog, int e,
                                       float (&A2)[NSTATE]) {
    bool st = true;
    float A0 = -__expf(Alog[e*NSTATE]);
    #pragma unroll
    for (int n = 0; n < NSTATE; n++) {
        float An = -__expf(Alog[e*NSTATE + n]);
        A2[n] = An * L2E;
        st = st && (fabsf(An - (n+1)*A0) <= 1e-5f * fabsf(An));
    }
    return st;
}

// ---------------- scan pass 1 ----------------
__global__ void k_scan1(const float* __restrict__ dt, const float* __restrict__ u,
                        const float* __restrict__ dbc, const float* __restrict__ Alog,
                        float* __restrict__ hN, float* __restrict__ P) {
    int e = blockIdx.x * 128 + threadIdx.x;
    int c = blockIdx.y, b = blockIdx.z;
    int rowbase = b * LSEQ + c * TCH;
    __shared__ float sB[TCH][NSTATE];
    for (int i = threadIdx.x; i < TCH*NSTATE; i += 128) {
        int r = i >> 4, n = i & 15;
        sB[r][n] = dbc[(size_t)(rowbase + r) * RBC + RRANK + n];
    }
    float A2[NSTATE];
    bool st = load_A(Alog, e, A2);
    __syncthreads();

    float h[NSTATE];
    #pragma unroll
    for (int n = 0; n < NSTATE; n++) h[n] = 0.f;
    float dts = 0.f;
    if (st) {
        for (int tt = 0; tt < TCH; tt++) {
            int row = rowbase + tt;
            float d  = dt[(size_t)row * EINNER + e];
            float uu = u [(size_t)row * EINNER + e];
            float du = d * uu;
            float w = fexp2n(d * A2[0]);
            float a = 1.0f;
            #pragma unroll
            for (int n = 0; n < NSTATE; n++) {
                a *= w;
                h[n] = fmaf(a, h[n], du * sB[tt][n]);
            }
            dts += d;
        }
    } else {
        for (int tt = 0; tt < TCH; tt++) {
            int row = rowbase + tt;
            float d  = dt[(size_t)row * EINNER + e];
            float uu = u [(size_t)row * EINNER + e];
            float du = d * uu;
            #pragma unroll
            for (int n = 0; n < NSTATE; n++) {
                float a = fexp2n(d * A2[n]);
                h[n] = fmaf(a, h[n], du * sB[tt][n]);
            }
            dts += d;
        }
    }
    int o = ((b * NCHUNK + c) * EINNER + e) * NSTATE;
    if (st) {
        float ws = fexp2n(dts * A2[0]);
        float a = 1.0f;
        #pragma unroll
        for (int n = 0; n < NSTATE; n++) { a *= ws; hN[o+n] = h[n]; P[o+n] = a; }
    } else {
        #pragma unroll
        for (int n = 0; n < NSTATE; n++) { hN[o+n] = h[n]; P[o+n] = fexp2n(dts * A2[n]); }
    }
}

// ---------------- scan pass 2: sequential chunk combine ----------------
__global__ void k_scan2(const float* __restrict__ hN, const float* __restrict__ P,
                        float* __restrict__ S) {
    int idx = blockIdx.x * blockDim.x + threadIdx.x;  // B*E*NSTATE
    int b = idx >> 14;
    int r = idx & 16383;
    float s = 0.f;
    int base = b * NCHUNK * EINNER * NSTATE + r;
    #pragma unroll
    for (int c = 0; c < NCHUNK; c++) {
        S[base + c * EINNER * NSTATE] = s;
        s = hN[base + c * EINNER * NSTATE] + P[base + c * EINNER * NSTATE] * s;
    }
}

// ---------------- scan pass 3: full scan + y + D skip + silu(z) -> bf16 planes ------
__global__ void k_scan3(const float* __restrict__ dt, const float* __restrict__ u,
                        const float* __restrict__ dbc, const float* __restrict__ xz,
                        const float* __restrict__ Alog, const float* __restrict__ Dv,
                        const float* __restrict__ S,
                        __nv_bfloat16* __restrict__ yh, __nv_bfloat16* __restrict__ yl) {
    int e = blockIdx.x * 128 + threadIdx.x;
    int c = blockIdx.y, b = blockIdx.z;
    int rowbase = b * LSEQ + c * TCH;
    __shared__ float sBC[TCH][2*NSTATE];
    for (int i = threadIdx.x; i < TCH*2*NSTATE; i += 128) {
        int r = i >> 5, n = i & 31;
        sBC[r][n] = dbc[(size_t)(rowbase + r) * RBC + RRANK + n];
    }
    float A2[NSTATE];
    bool st = load_A(Alog, e, A2);
    float Dd = Dv[e];
    float h[NSTATE];
    int o = ((b * NCHUNK + c) * EINNER + e) * NSTATE;
    #pragma unroll
    for (int n = 0; n < NSTATE; n++) h[n] = S[o + n];
    __syncthreads();

    for (int tt = 0; tt < TCH; tt++) {
        int row = rowbase + tt;
        float d  = dt[(size_t)row * EINNER + e];
        float uu = u [(size_t)row * EINNER + e];
        float zz = xz[(size_t)row * 2 * EINNER + EINNER + e];
        float du = d * uu;
        float acc = 0.f;
        if (st) {
            float w = fexp2n(d * A2[0]);
            float a = 1.0f;
            #pragma unroll
            for (int n = 0; n < NSTATE; n++) {
                a *= w;
                h[n] = fmaf(a, h[n], du * sBC[tt][n]);
                acc = fmaf(h[n], sBC[tt][NSTATE + n], acc);
            }
        } else {
            #pragma unroll
            for (int n = 0; n < NSTATE; n++) {
                float a = fexp2n(d * A2[n]);
                h[n] = fmaf(a, h[n], du * sBC[tt][n]);
                acc = fmaf(h[n], sBC[tt][NSTATE + n], acc);
            }
        }
        acc = fmaf(uu, Dd, acc);
        float sz = zz / (1.0f + __expf(-zz));
        float yv = acc * sz;
        __nv_bfloat16 hh, ll; split_bf16(yv, hh, ll);
        size_t oi = (size_t)row * EINNER + e;
        yh[oi] = hh; yl[oi] = ll;
    }
}

// ---------------- launcher ----------------
extern "C" void kernel_launch(void* const* d_in, const int* in_sizes, int n_in,
                              void* d_out, int out_size) {
    const float* x     = (const float*)d_in[0];
    const float* pos   = (const float*)d_in[1];
    const float* normw = (const float*)d_in[2];
    const float* inw   = (const float*)d_in[3];
    const float* convw = (const float*)d_in[4];
    const float* convb = (const float*)d_in[5];
    const float* xpw   = (const float*)d_in[6];
    const float* dtw   = (const float*)d_in[7];
    const float* dtb   = (const float*)d_in[8];
    const float* alog  = (const float*)d_in[9];
    const float* dvec  = (const float*)d_in[10];
    const float* outw  = (const float*)d_in[11];
    float* out = (float*)d_out;
    (void)in_sizes; (void)n_in; (void)out_size;

    float *ph, *pxz, *pxi, *pdbcp, *pdbc, *pdt, *phN, *pP, *pS;
    __nv_bfloat16 *pwh, *pwl, *pxnh, *pxnl, *pxih, *pxil, *pdbch, *pdbcl, *pyh, *pyl;
    cudaGetSymbolAddress((void**)&ph,    g_h);
    cudaGetSymbolAddress((void**)&pxz,   g_xz);
    cudaGetSymbolAddress((void**)&pxi,   g_xi);
    cudaGetSymbolAddress((void**)&pdbcp, g_dbcp);
    cudaGetSymbolAddress((void**)&pdbc,  g_dbc);
    cudaGetSymbolAddress((void**)&pdt,   g_dt);
    cudaGetSymbolAddress((void**)&phN,   g_hN);
    cudaGetSymbolAddress((void**)&pP,    g_P);
    cudaGetSymbolAddress((void**)&pS,    g_S);
    cudaGetSymbolAddress((void**)&pwh,   g_wh);
    cudaGetSymbolAddress((void**)&pwl,   g_wl);
    cudaGetSymbolAddress((void**)&pxnh,  g_xnh);
    cudaGetSymbolAddress((void**)&pxnl,  g_xnl);
    cudaGetSymbolAddress((void**)&pxih,  g_xih);
    cudaGetSymbolAddress((void**)&pxil,  g_xil);
    cudaGetSymbolAddress((void**)&pdbch, g_dbch);
    cudaGetSymbolAddress((void**)&pdbcl, g_dbcl);
    cudaGetSymbolAddress((void**)&pyh,   g_yh);
    cudaGetSymbolAddress((void**)&pyl,   g_yl);

    k_cvtw<<<(N_WTOT/4 + 255)/256, 256>>>(inw, xpw, dtw, outw, pwh, pwl);

    for (int l = 0; l < NLAYERS; l++) {
        const float* hin = (l == 0) ? x : ph;
        // 1. h+pos -> rmsnorm -> xn planes
        k_addnorm<<<TTOK, 128>>>(hin, pos, normw, pxnh, pxnl);
        // 2. in_proj -> xz fp32 (2048,2048); grid 32x32
        k_mma<0><<<dim3(2*EINNER/64, TTOK/64, 1), 128>>>(
            pxnh, pxnl, pwh + OFF_IN + (size_t)l*2*EINNER*DMODEL,
            pwl + OFF_IN + (size_t)l*2*EINNER*DMODEL, pxz,
            DMODEL, DMODEL, DMODEL, 2*EINNER, nullptr, 0);
        // 3. conv + SiLU -> xi fp32 + planes (4 tokens/thread)
        k_conv<<<(TTOK*EINNER/4)/256, 256>>>(pxz, convw + (size_t)l*EINNER*4,
                                             convb + (size_t)l*EINNER, pxi, pxih, pxil);
        // 4. x_proj split-K=8 + reduce -> dbc fp32 + planes
        k_mma<0><<<dim3(1, TTOK/64, 8), 128>>>(
            pxih, pxil, pwh + OFF_XP + (size_t)l*RBC*EINNER,
            pwl + OFF_XP + (size_t)l*RBC*EINNER, pdbcp,
            EINNER, EINNER, EINNER, RBC, nullptr, TTOK*RBC);
        k_reduce8<<<(TTOK*RBC)/256, 256>>>(pdbcp, pdbc, pdbch, pdbcl, TTOK*RBC);
        // 5. dt_proj + softplus(+bias) -> dt fp32; grid 16x32
        k_mma<1><<<dim3(EINNER/64, TTOK/64, 1), 128>>>(
            pdbch, pdbcl, pwh + OFF_DT + (size_t)l*EINNER*RRANK,
            pwl + OFF_DT + (size_t)l*EINNER*RRANK, pdt,
            RRANK, RBC, RRANK, EINNER, dtb + (size_t)l*EINNER, 0);
        // 6. chunked selective scan (32 chunks)
        k_scan1<<<dim3(EINNER/128, NCHUNK, BATCH), 128>>>(pdt, pxi, pdbc,
                                                          alog + (size_t)l*EINNER*NSTATE,
                                                          phN, pP);
        k_scan2<<<(BATCH*EINNER*NSTATE)/256, 256>>>(phN, pP, pS);
        k_scan3<<<dim3(EINNER/128, NCHUNK, BATCH), 128>>>(pdt, pxi, pdbc, pxz,
                                                          alog + (size_t)l*EINNER*NSTATE,
                                                          dvec + (size_t)l*EINNER, pS,
                                                          pyh, pyl);
        // 7. out_proj -> next h (or final output); grid 8x32
        float* dest = (l == NLAYERS-1) ? out : ph;
        k_mma<0><<<dim3(DMODEL/64, TTOK/64, 1), 128>>>(
            pyh, pyl, pwh + OFF_OUT + (size_t)l*DMODEL*EINNER,
            pwl + OFF_OUT + (size_t)l*DMODEL*EINNER, dest,
            EINNER, EINNER, EINNER, DMODEL, nullptr, 0);
    }
}

// round 5
// speedup vs baseline: 2.8985x; 1.0582x over previous
#include <cuda_runtime.h>
#include <cuda_bf16.h>
#include <math.h>

// ---------------- problem constants ----------------
#define NLAYERS 6
#define BATCH   2
#define LSEQ    1024
#define DMODEL  512
#define EINNER  1024
#define NSTATE  16
#define RRANK   32
#define RBC     64            // RRANK + 2*NSTATE
#define TTOK    (BATCH*LSEQ)  // 2048
#define NCHUNK  64
#define TCH     (LSEQ/NCHUNK) // 16
#define EPSF    1.1920929e-07f
#define L2E     1.4426950408889634f

// weight plane layout (bf16 hi/lo), element offsets
#define N_IN   (NLAYERS*2*EINNER*DMODEL)
#define N_XP   (NLAYERS*RBC*EINNER)
#define N_DT   (NLAYERS*EINNER*RRANK)
#define N_OUT  (NLAYERS*DMODEL*EINNER)
#define OFF_IN  0
#define OFF_XP  (N_IN)
#define OFF_DT  (N_IN+N_XP)
#define OFF_OUT (N_IN+N_XP+N_DT)
#define N_WTOT  (N_IN+N_XP+N_DT+N_OUT)

// ---------------- scratch ----------------
__device__ float g_h   [TTOK*DMODEL];
__device__ float g_xz  [TTOK*2*EINNER];
__device__ float g_xi  [TTOK*EINNER];
__device__ float g_dbcp[8*TTOK*RBC];
__device__ float g_dbc [TTOK*RBC];
__device__ float g_dt  [TTOK*EINNER];
__device__ float g_ya  [TTOK*EINNER];   // local scan output (pre-correction)
__device__ float g_cum [TTOK*EINNER];   // inclusive cumsum of dt within chunk
__device__ float g_hN  [BATCH*NCHUNK*EINNER*NSTATE];
__device__ float g_P   [BATCH*NCHUNK*EINNER*NSTATE];
__device__ float g_S   [BATCH*NCHUNK*EINNER*NSTATE];
__device__ __nv_bfloat16 g_wh [N_WTOT], g_wl [N_WTOT];
__device__ __nv_bfloat16 g_xnh[TTOK*DMODEL],  g_xnl[TTOK*DMODEL];
__device__ __nv_bfloat16 g_xih[TTOK*EINNER],  g_xil[TTOK*EINNER];
__device__ __nv_bfloat16 g_dbch[TTOK*RBC],    g_dbcl[TTOK*RBC];
__device__ __nv_bfloat16 g_yh [TTOK*EINNER],  g_yl [TTOK*EINNER];

__device__ __forceinline__ void split_bf16(float v, __nv_bfloat16& h, __nv_bfloat16& l) {
    h = __float2bfloat16(v);
    l = __float2bfloat16(v - __bfloat162float(h));
}

// fast exp2 on FMA pipe, x <= 0; clamps at -126
__device__ __forceinline__ float fexp2n(float x) {
    x = fmaxf(x, -126.0f);
    float t = x + 12582912.0f;
    int   i = __float_as_int(t) - 0x4B400000;
    float r = x - (t - 12582912.0f);
    float p =          1.3333558e-3f;
    p = fmaf(p, r, 9.6181291e-3f);
    p = fmaf(p, r, 5.5504109e-2f);
    p = fmaf(p, r, 2.4022651e-1f);
    p = fmaf(p, r, 6.9314718e-1f);
    p = fmaf(p, r, 1.0f);
    return __int_as_float(__float_as_int(p) + (i << 23));
}

__device__ __forceinline__ float softplusf(float x) {
    return fmaxf(x, 0.0f) + log1pf(__expf(-fabsf(x)));
}

#define LDSM4(r0,r1,r2,r3,addr) \
    asm volatile("ldmatrix.sync.aligned.m8n8.x4.shared.b16 {%0,%1,%2,%3}, [%4];" \
        : "=r"(r0), "=r"(r1), "=r"(r2), "=r"(r3) : "r"(addr))

// ---------------- K0: weights -> bf16 hi/lo planes ----------------
__global__ void k_cvtw(const float* __restrict__ inw, const float* __restrict__ xpw,
                       const float* __restrict__ dtw, const float* __restrict__ outw,
                       __nv_bfloat16* __restrict__ wh, __nv_bfloat16* __restrict__ wl) {
    int i4 = blockIdx.x * blockDim.x + threadIdx.x;
    int e0 = i4 * 4;
    if (e0 >= N_WTOT) return;
    const float* src; int off;
    if      (e0 < OFF_XP)  { src = inw;  off = e0 - OFF_IN;  }
    else if (e0 < OFF_DT)  { src = xpw;  off = e0 - OFF_XP;  }
    else if (e0 < OFF_OUT) { src = dtw;  off = e0 - OFF_DT;  }
    else                   { src = outw; off = e0 - OFF_OUT; }
    float4 v = *(const float4*)(src + off);
    __nv_bfloat16 h0,h1,h2,h3,l0,l1,l2,l3;
    split_bf16(v.x,h0,l0); split_bf16(v.y,h1,l1);
    split_bf16(v.z,h2,l2); split_bf16(v.w,h3,l3);
    *(__nv_bfloat162*)&wh[e0]   = __nv_bfloat162(h0,h1);
    *(__nv_bfloat162*)&wh[e0+2] = __nv_bfloat162(h2,h3);
    *(__nv_bfloat162*)&wl[e0]   = __nv_bfloat162(l0,l1);
    *(__nv_bfloat162*)&wl[e0+2] = __nv_bfloat162(l2,l3);
}

// ---------------- K1: h+pos then RMSNorm -> bf16 hi/lo ----------------
__global__ void k_addnorm(const float* __restrict__ hin, const float* __restrict__ pos,
                          const float* __restrict__ nw,
                          __nv_bfloat16* __restrict__ oh, __nv_bfloat16* __restrict__ ol) {
    int t = blockIdx.x;
    int tid = threadIdx.x;        // 128 threads * float4 = 512
    float4 v  = ((const float4*)(hin + t*DMODEL))[tid];
    float4 pv = ((const float4*)(pos + t*DMODEL))[tid];
    v.x += pv.x; v.y += pv.y; v.z += pv.z; v.w += pv.w;
    float ss = v.x*v.x + v.y*v.y + v.z*v.z + v.w*v.w;
    #pragma unroll
    for (int o = 16; o > 0; o >>= 1) ss += __shfl_xor_sync(0xffffffffu, ss, o);
    __shared__ float sred[4];
    if ((tid & 31) == 0) sred[tid >> 5] = ss;
    __syncthreads();
    ss = sred[0] + sred[1] + sred[2] + sred[3];
    float s = rsqrtf(ss * (1.0f/DMODEL) + EPSF);
    float4 w = ((const float4*)nw)[tid];
    float o0 = v.x*s*w.x, o1 = v.y*s*w.y, o2 = v.z*s*w.z, o3 = v.w*s*w.w;
    __nv_bfloat16 h0,h1,h2,h3,l0,l1,l2,l3;
    split_bf16(o0,h0,l0); split_bf16(o1,h1,l1);
    split_bf16(o2,h2,l2); split_bf16(o3,h3,l3);
    int base = t*DMODEL + tid*4;
    *(__nv_bfloat162*)&oh[base]   = __nv_bfloat162(h0,h1);
    *(__nv_bfloat162*)&oh[base+2] = __nv_bfloat162(h2,h3);
    *(__nv_bfloat162*)&ol[base]   = __nv_bfloat162(l0,l1);
    *(__nv_bfloat162*)&ol[base+2] = __nv_bfloat162(l2,l3);
}

// ---------------- bf16-split MMA GEMM, double-buffered smem + ldmatrix ----------------
__device__ __forceinline__ void mma_bf16(float (&d)[4], const unsigned (&a)[4],
                                         const unsigned (&b)[2]) {
    asm volatile(
        "mma.sync.aligned.m16n8k16.row.col.f32.bf16.bf16.f32 "
        "{%0,%1,%2,%3}, {%4,%5,%6,%7}, {%8,%9}, {%0,%1,%2,%3};\n"
        : "+f"(d[0]), "+f"(d[1]), "+f"(d[2]), "+f"(d[3])
        : "r"(a[0]), "r"(a[1]), "r"(a[2]), "r"(a[3]), "r"(b[0]), "r"(b[1]));
}

// BM=BN=64, 4 warps (128 thr), BK=32, 3-term bf16-split, double buffer, LDSM frags.
template<int EPI>
__global__ void __launch_bounds__(128)
k_mma(const __nv_bfloat16* __restrict__ Agh, const __nv_bfloat16* __restrict__ Agl,
      const __nv_bfloat16* __restrict__ Bgh, const __nv_bfloat16* __restrict__ Bgl,
      float* __restrict__ C, int K, int lda, int ldw, int ldc,
      const float* __restrict__ bias, int pstride)
{
    constexpr int BM = 64, BN = 64, BK = 32, THREADS = 128;
    constexpr int TM = 2, TN = 4;               // WM=32, WN=32
    constexpr int LST = BK + 8;                 // 40 bf16 per smem row (80B)
    constexpr int BUFB = BM*LST*2;              // bytes per smem buffer

    __shared__ __align__(16) __nv_bfloat16 Ah[2][BM*LST], Al[2][BM*LST];
    __shared__ __align__(16) __nv_bfloat16 Bh[2][BN*LST], Bl[2][BN*LST];

    const int tid  = threadIdx.x;
    const int lane = tid & 31;
    const int warp = tid >> 5;
    const int wm = (warp >> 1) * 32;
    const int wn = (warp & 1) * 32;
    const int m0 = blockIdx.y * BM, n0 = blockIdx.x * BN;
    const int kLen = K / gridDim.z;
    const int k0 = blockIdx.z * kLen;
    const int niter = kLen / BK;

    // ldmatrix per-lane address components (element units)
    const int laneq = lane & 7;
    const int a_rowoff = (wm + laneq + ((lane>>3)&1)*8) * LST;
    const int a_koff   = (lane>>4)*8;
    const int b_rowoff = (wn + (lane>>4)*8 + laneq) * LST;
    const int b_koff   = ((lane>>3)&1)*8;

    const unsigned uAh = (unsigned)__cvta_generic_to_shared(&Ah[0][0]);
    const unsigned uAl = (unsigned)__cvta_generic_to_shared(&Al[0][0]);
    const unsigned uBh = (unsigned)__cvta_generic_to_shared(&Bh[0][0]);
    const unsigned uBl = (unsigned)__cvta_generic_to_shared(&Bl[0][0]);

    float acc[TM][TN][4];
    #pragma unroll
    for (int i = 0; i < TM; i++)
        #pragma unroll
        for (int j = 0; j < TN; j++)
            #pragma unroll
            for (int q = 0; q < 4; q++) acc[i][j][q] = 0.0f;

    uint4 sAh[2], sAl[2], sBh[2], sBl[2];
    const int r_  = tid >> 2,            kc_  = tid & 3;
    const int r2_ = (tid + THREADS) >> 2, kc2_ = (tid + THREADS) & 3;
    const int o0 = r_*LST + kc_*8, o1 = r2_*LST + kc2_*8;

    // prologue: tile 0 -> regs -> smem buf 0
    {
        size_t gA0 = (size_t)(m0 + r_ ) * lda + k0 + kc_ *8;
        size_t gA1 = (size_t)(m0 + r2_) * lda + k0 + kc2_*8;
        size_t gB0 = (size_t)(n0 + r_ ) * ldw + k0 + kc_ *8;
        size_t gB1 = (size_t)(n0 + r2_) * ldw + k0 + kc2_*8;
        sAh[0] = *(const uint4*)&Agh[gA0]; sAl[0] = *(const uint4*)&Agl[gA0];
        sAh[1] = *(const uint4*)&Agh[gA1]; sAl[1] = *(const uint4*)&Agl[gA1];
        sBh[0] = *(const uint4*)&Bgh[gB0]; sBl[0] = *(const uint4*)&Bgl[gB0];
        sBh[1] = *(const uint4*)&Bgh[gB1]; sBl[1] = *(const uint4*)&Bgl[gB1];
        *(uint4*)&Ah[0][o0] = sAh[0]; *(uint4*)&Al[0][o0] = sAl[0];
        *(uint4*)&Ah[0][o1] = sAh[1]; *(uint4*)&Al[0][o1] = sAl[1];
        *(uint4*)&Bh[0][o0] = sBh[0]; *(uint4*)&Bl[0][o0] = sBl[0];
        *(uint4*)&Bh[0][o1] = sBh[1]; *(uint4*)&Bl[0][o1] = sBl[1];
    }
    __syncthreads();

    for (int kt = 0; kt < niter; kt++) {
        const int cur = kt & 1;
        const bool more = (kt + 1 < niter);
        if (more) {
            int kb = k0 + (kt+1)*BK;
            size_t gA0 = (size_t)(m0 + r_ ) * lda + kb + kc_ *8;
            size_t gA1 = (size_t)(m0 + r2_) * lda + kb + kc2_*8;
            size_t gB0 = (size_t)(n0 + r_ ) * ldw + kb + kc_ *8;
            size_t gB1 = (size_t)(n0 + r2_) * ldw + kb + kc2_*8;
            sAh[0] = *(const uint4*)&Agh[gA0]; sAl[0] = *(const uint4*)&Agl[gA0];
            sAh[1] = *(const uint4*)&Agh[gA1]; sAl[1] = *(const uint4*)&Agl[gA1];
            sBh[0] = *(const uint4*)&Bgh[gB0]; sBl[0] = *(const uint4*)&Bgl[gB0];
            sBh[1] = *(const uint4*)&Bgh[gB1]; sBl[1] = *(const uint4*)&Bgl[gB1];
        }

        const int bufB = cur * BUFB;
        #pragma unroll
        for (int s = 0; s < 2; s++) {
            // B fragments: 2 LDSM.x4 per plane cover all TN=4 n8k16 frags
            unsigned bhf[TN][2], blf[TN][2];
            {
                int boff = bufB + (b_rowoff + s*16 + b_koff) * 2;
                unsigned t0,t1,t2,t3;
                LDSM4(t0,t1,t2,t3, uBh + boff);
                bhf[0][0]=t0; bhf[0][1]=t1; bhf[1][0]=t2; bhf[1][1]=t3;
                LDSM4(t0,t1,t2,t3, uBh + boff + 16*LST*2);
                bhf[2][0]=t0; bhf[2][1]=t1; bhf[3][0]=t2; bhf[3][1]=t3;
                LDSM4(t0,t1,t2,t3, uBl + boff);
                blf[0][0]=t0; blf[0][1]=t1; blf[1][0]=t2; blf[1][1]=t3;
                LDSM4(t0,t1,t2,t3, uBl + boff + 16*LST*2);
                blf[2][0]=t0; blf[2][1]=t1; blf[3][0]=t2; blf[3][1]=t3;
            }
            #pragma unroll
            for (int i = 0; i < TM; i++) {
                int aoff = bufB + (a_rowoff + i*16*LST + s*16 + a_koff) * 2;
                unsigned ahf[4], alf[4];
                LDSM4(ahf[0],ahf[1],ahf[2],ahf[3], uAh + aoff);
                LDSM4(alf[0],alf[1],alf[2],alf[3], uAl + aoff);
                #pragma unroll
                for (int j = 0; j < TN; j++) {
                    mma_bf16(acc[i][j], ahf, bhf[j]);
                    mma_bf16(acc[i][j], ahf, blf[j]);
                    mma_bf16(acc[i][j], alf, bhf[j]);
                }
            }
        }

        if (more) {
            int nxt = cur ^ 1;
            *(uint4*)&Ah[nxt][o0] = sAh[0]; *(uint4*)&Al[nxt][o0] = sAl[0];
            *(uint4*)&Ah[nxt][o1] = sAh[1]; *(uint4*)&Al[nxt][o1] = sAl[1];
            *(uint4*)&Bh[nxt][o0] = sBh[0]; *(uint4*)&Bl[nxt][o0] = sBl[0];
            *(uint4*)&Bh[nxt][o1] = sBh[1]; *(uint4*)&Bl[nxt][o1] = sBl[1];
        }
        __syncthreads();
    }

    float* Cp = C + (size_t)blockIdx.z * pstride;
    #pragma unroll
    for (int i = 0; i < TM; i++) {
        int row = m0 + wm + i*16 + (lane >> 2);
        #pragma unroll
        for (int j = 0; j < TN; j++) {
            int col = n0 + wn + j*8 + (lane & 3)*2;
            float2 v0, v1;
            if (EPI == 1) {
                float b0 = bias[col], b1 = bias[col+1];
                v0.x = softplusf(acc[i][j][0] + b0);
                v0.y = softplusf(acc[i][j][1] + b1);
                v1.x = softplusf(acc[i][j][2] + b0);
                v1.y = softplusf(acc[i][j][3] + b1);
            } else {
                v0.x = acc[i][j][0]; v0.y = acc[i][j][1];
                v1.x = acc[i][j][2]; v1.y = acc[i][j][3];
            }
            *(float2*)&Cp[(size_t)row * ldc + col]     = v0;
            *(float2*)&Cp[(size_t)(row+8) * ldc + col] = v1;
        }
    }
}

// ---------------- K3: causal depthwise conv (k=4) + bias + SiLU, 4 tokens/thread ----
__global__ void k_conv(const float* __restrict__ xz, const float* __restrict__ cw,
                       const float* __restrict__ cb, float* __restrict__ xi,
                       __nv_bfloat16* __restrict__ xih, __nv_bfloat16* __restrict__ xil) {
    int idx = blockIdx.x * blockDim.x + threadIdx.x;   // over B*(L/4)*E
    int e  = idx & (EINNER - 1);
    int lg = (idx >> 10) & (LSEQ/4 - 1);
    int b  = idx >> 18;
    int l0 = lg * 4;
    const float* base = xz + (size_t)(b * LSEQ) * 2 * EINNER + e;
    float xv[7];
    #pragma unroll
    for (int j = 0; j < 7; j++) {
        int li = l0 - 3 + j;
        xv[j] = (li >= 0) ? base[(size_t)li * 2 * EINNER] : 0.0f;
    }
    float w0 = cw[e*4+0], w1 = cw[e*4+1], w2 = cw[e*4+2], w3 = cw[e*4+3];
    float bb = cb[e];
    #pragma unroll
    for (int t = 0; t < 4; t++) {
        float acc = bb;
        acc = fmaf(w0, xv[t+0], acc);
        acc = fmaf(w1, xv[t+1], acc);
        acc = fmaf(w2, xv[t+2], acc);
        acc = fmaf(w3, xv[t+3], acc);
        float v = acc / (1.0f + __expf(-acc));
        size_t oi = (size_t)(b*LSEQ + l0 + t) * EINNER + e;
        xi[oi] = v;
        __nv_bfloat16 h, lo; split_bf16(v, h, lo);
        xih[oi] = h; xil[oi] = lo;
    }
}

// ---------------- split-K reduce for x_proj (+ bf16 planes) ----------------
__global__ void k_reduce8(const float* __restrict__ part, float* __restrict__ out,
                          __nv_bfloat16* __restrict__ oh, __nv_bfloat16* __restrict__ ol,
                          int n) {
    int i = blockIdx.x * blockDim.x + threadIdx.x;
    if (i < n) {
        float s = 0.f;
        #pragma unroll
        for (int z = 0; z < 8; z++) s += part[(size_t)z * n + i];
        out[i] = s;
        __nv_bfloat16 h, lo; split_bf16(s, h, lo);
        oh[i] = h; ol[i] = lo;
    }
}

// ---------------- A setup helper: detect A[n] = (n+1)*A[0] structure --------------
__device__ __forceinline__ bool load_A(const float* __restrict__ Alog, int e,
                                       float (&A2)[NSTATE]) {
    bool st = true;
    float A0 = -__expf(Alog[e*NSTATE]);
    #pragma unroll
    for (int n = 0; n < NSTATE; n++) {
        float An = -__expf(Alog[e*NSTATE + n]);
        A2[n] = An * L2E;
        st = st && (fabsf(An - (n+1)*A0) <= 1e-5f * fabsf(An));
    }
    return st;
}

// ---------------- scan pass 1: local scan + local output + cumdt + chunk summary ----
__global__ void k_scan1(const float* __restrict__ dt, const float* __restrict__ u,
                        const float* __restrict__ dbc, const float* __restrict__ Alog,
                        float* __restrict__ hN, float* __restrict__ P,
                        float* __restrict__ yacc, float* __restrict__ cum) {
    int e = blockIdx.x * 128 + threadIdx.x;
    int c = blockIdx.y, b = blockIdx.z;
    int rowbase = b * LSEQ + c * TCH;
    __shared__ float sBC[TCH][2*NSTATE];
    for (int i = threadIdx.x; i < TCH*2*NSTATE; i += 128) {
        int r = i >> 5, n = i & 31;
        sBC[r][n] = dbc[(size_t)(rowbase + r) * RBC + RRANK + n];
    }
    float A2[NSTATE];
    bool st = load_A(Alog, e, A2);
    __syncthreads();

    float h[NSTATE];
    #pragma unroll
    for (int n = 0; n < NSTATE; n++) h[n] = 0.f;
    float cumd = 0.f;
    for (int tt = 0; tt < TCH; tt++) {
        int row = rowbase + tt;
        float d  = dt[(size_t)row * EINNER + e];
        float uu = u [(size_t)row * EINNER + e];
        float du = d * uu;
        float acc = 0.f;
        if (st) {
            float w = fexp2n(d * A2[0]);
            float a = 1.0f;
            #pragma unroll
            for (int n = 0; n < NSTATE; n++) {
                a *= w;
                h[n] = fmaf(a, h[n], du * sBC[tt][n]);
                acc = fmaf(h[n], sBC[tt][NSTATE + n], acc);
            }
        } else {
            #pragma unroll
            for (int n = 0; n < NSTATE; n++) {
                float a = fexp2n(d * A2[n]);
                h[n] = fmaf(a, h[n], du * sBC[tt][n]);
                acc = fmaf(h[n], sBC[tt][NSTATE + n], acc);
            }
        }
        cumd += d;
        size_t oi = (size_t)row * EINNER + e;
        yacc[oi] = acc;
        cum[oi]  = cumd;
    }
    int o = ((b * NCHUNK + c) * EINNER + e) * NSTATE;
    if (st) {
        float ws = fexp2n(cumd * A2[0]);
        float a = 1.0f;
        #pragma unroll
        for (int n = 0; n < NSTATE; n++) { a *= ws; hN[o+n] = h[n]; P[o+n] = a; }
    } else {
        #pragma unroll
        for (int n = 0; n < NSTATE; n++) { hN[o+n] = h[n]; P[o+n] = fexp2n(cumd * A2[n]); }
    }
}

// ---------------- scan pass 2: sequential chunk combine ----------------
__global__ void k_scan2(const float* __restrict__ hN, const float* __restrict__ P,
                        float* __restrict__ S) {
    int idx = blockIdx.x * blockDim.x + threadIdx.x;  // B*E*NSTATE
    int b = idx >> 14;
    int r = idx & 16383;
    float s = 0.f;
    int base = b * NCHUNK * EINNER * NSTATE + r;
    #pragma unroll 8
    for (int c = 0; c < NCHUNK; c++) {
        S[base + c * EINNER * NSTATE] = s;
        s = hN[base + c * EINNER * NSTATE] + P[base + c * EINNER * NSTATE] * s;
    }
}

// ---------------- scan pass 3: PARALLEL correction + D skip + silu(z) -> bf16 -------
__global__ void k_scan3(const float* __restrict__ u, const float* __restrict__ dbc,
                        const float* __restrict__ xz, const float* __restrict__ Alog,
                        const float* __restrict__ Dv, const float* __restrict__ S,
                        const float* __restrict__ yacc, const float* __restrict__ cum,
                        __nv_bfloat16* __restrict__ yh, __nv_bfloat16* __restrict__ yl) {
    int e = blockIdx.x * 128 + threadIdx.x;
    int c = blockIdx.y, b = blockIdx.z;
    int rowbase = b * LSEQ + c * TCH;
    __shared__ float sC[TCH][NSTATE];
    for (int i = threadIdx.x; i < TCH*NSTATE; i += 128) {
        int r = i >> 4, n = i & 15;
        sC[r][n] = dbc[(size_t)(rowbase + r) * RBC + RRANK + NSTATE + n];
    }
    float A2[NSTATE];
    bool st = load_A(Alog, e, A2);
    float Dd = Dv[e];
    float sreg[NSTATE];
    int o = ((b * NCHUNK + c) * EINNER + e) * NSTATE;
    #pragma unroll
    for (int n = 0; n < NSTATE; n++) sreg[n] = S[o + n];
    __syncthreads();

    for (int tt = 0; tt < TCH; tt++) {
        int row = rowbase + tt;
        size_t oi = (size_t)row * EINNER + e;
        float cd = cum[oi];
        float acc = yacc[oi];
        float uu  = u[oi];
        float zz  = xz[(size_t)row * 2 * EINNER + EINNER + e];
        if (st) {
            float wS = fexp2n(cd * A2[0]);
            float a = 1.0f;
            #pragma unroll
            for (int n = 0; n < NSTATE; n++) {
                a *= wS;
                acc = fmaf(a * sreg[n], sC[tt][n], acc);
            }
        } else {
            #pragma unroll
            for (int n = 0; n < NSTATE; n++)
                acc = fmaf(fexp2n(cd * A2[n]) * sreg[n], sC[tt][n], acc);
        }
        acc = fmaf(uu, Dd, acc);
        float sz = zz / (1.0f + __expf(-zz));
        float yv = acc * sz;
        __nv_bfloat16 hh, ll; split_bf16(yv, hh, ll);
        yh[oi] = hh; yl[oi] = ll;
    }
}

// ---------------- launcher ----------------
extern "C" void kernel_launch(void* const* d_in, const int* in_sizes, int n_in,
                              void* d_out, int out_size) {
    const float* x     = (const float*)d_in[0];
    const float* pos   = (const float*)d_in[1];
    const float* normw = (const float*)d_in[2];
    const float* inw   = (const float*)d_in[3];
    const float* convw = (const float*)d_in[4];
    const float* convb = (const float*)d_in[5];
    const float* xpw   = (const float*)d_in[6];
    const float* dtw   = (const float*)d_in[7];
    const float* dtb   = (const float*)d_in[8];
    const float* alog  = (const float*)d_in[9];
    const float* dvec  = (const float*)d_in[10];
    const float* outw  = (const float*)d_in[11];
    float* out = (float*)d_out;
    (void)in_sizes; (void)n_in; (void)out_size;

    float *ph, *pxz, *pxi, *pdbcp, *pdbc, *pdt, *pya, *pcum, *phN, *pP, *pS;
    __nv_bfloat16 *pwh, *pwl, *pxnh, *pxnl, *pxih, *pxil, *pdbch, *pdbcl, *pyh, *pyl;
    cudaGetSymbolAddress((void**)&ph,    g_h);
    cudaGetSymbolAddress((void**)&pxz,   g_xz);
    cudaGetSymbolAddress((void**)&pxi,   g_xi);
    cudaGetSymbolAddress((void**)&pdbcp, g_dbcp);
    cudaGetSymbolAddress((void**)&pdbc,  g_dbc);
    cudaGetSymbolAddress((void**)&pdt,   g_dt);
    cudaGetSymbolAddress((void**)&pya,   g_ya);
    cudaGetSymbolAddress((void**)&pcum,  g_cum);
    cudaGetSymbolAddress((void**)&phN,   g_hN);
    cudaGetSymbolAddress((void**)&pP,    g_P);
    cudaGetSymbolAddress((void**)&pS,    g_S);
    cudaGetSymbolAddress((void**)&pwh,   g_wh);
    cudaGetSymbolAddress((void**)&pwl,   g_wl);
    cudaGetSymbolAddress((void**)&pxnh,  g_xnh);
    cudaGetSymbolAddress((void**)&pxnl,  g_xnl);
    cudaGetSymbolAddress((void**)&pxih,  g_xih);
    cudaGetSymbolAddress((void**)&pxil,  g_xil);
    cudaGetSymbolAddress((void**)&pdbch, g_dbch);
    cudaGetSymbolAddress((void**)&pdbcl, g_dbcl);
    cudaGetSymbolAddress((void**)&pyh,   g_yh);
    cudaGetSymbolAddress((void**)&pyl,   g_yl);

    k_cvtw<<<(N_WTOT/4 + 255)/256, 256>>>(inw, xpw, dtw, outw, pwh, pwl);

    for (int l = 0; l < NLAYERS; l++) {
        const float* hin = (l == 0) ? x : ph;
        // 1. h+pos -> rmsnorm -> xn planes
        k_addnorm<<<TTOK, 128>>>(hin, pos, normw, pxnh, pxnl);
        // 2. in_proj -> xz fp32 (2048,2048)
        k_mma<0><<<dim3(2*EINNER/64, TTOK/64, 1), 128>>>(
            pxnh, pxnl, pwh + OFF_IN + (size_t)l*2*EINNER*DMODEL,
            pwl + OFF_IN + (size_t)l*2*EINNER*DMODEL, pxz,
            DMODEL, DMODEL, DMODEL, 2*EINNER, nullptr, 0);
        // 3. conv + SiLU -> xi fp32 + planes
        k_conv<<<(TTOK*EINNER/4)/256, 256>>>(pxz, convw + (size_t)l*EINNER*4,
                                             convb + (size_t)l*EINNER, pxi, pxih, pxil);
        // 4. x_proj split-K=8 + reduce -> dbc fp32 + planes
        k_mma<0><<<dim3(1, TTOK/64, 8), 128>>>(
            pxih, pxil, pwh + OFF_XP + (size_t)l*RBC*EINNER,
            pwl + OFF_XP + (size_t)l*RBC*EINNER, pdbcp,
            EINNER, EINNER, EINNER, RBC, nullptr, TTOK*RBC);
        k_reduce8<<<(TTOK*RBC)/256, 256>>>(pdbcp, pdbc, pdbch, pdbcl, TTOK*RBC);
        // 5. dt_proj + softplus(+bias) -> dt fp32
        k_mma<1><<<dim3(EINNER/64, TTOK/64, 1), 128>>>(
            pdbch, pdbcl, pwh + OFF_DT + (size_t)l*EINNER*RRANK,
            pwl + OFF_DT + (size_t)l*EINNER*RRANK, pdt,
            RRANK, RBC, RRANK, EINNER, dtb + (size_t)l*EINNER, 0);
        // 6. scan: 1 sequential pass + combine + parallel correction
        k_scan1<<<dim3(EINNER/128, NCHUNK, BATCH), 128>>>(pdt, pxi, pdbc,
                                                          alog + (size_t)l*EINNER*NSTATE,
                                                          phN, pP, pya, pcum);
        k_scan2<<<(BATCH*EINNER*NSTATE)/256, 256>>>(phN, pP, pS);
        k_scan3<<<dim3(EINNER/128, NCHUNK, BATCH), 128>>>(pxi, pdbc, pxz,
                                                          alog + (size_t)l*EINNER*NSTATE,
                                                          dvec + (size_t)l*EINNER, pS,
                                                          pya, pcum, pyh, pyl);
        // 7. out_proj -> next h (or final output)
        float* dest = (l == NLAYERS-1) ? out : ph;
        k_mma<0><<<dim3(DMODEL/64, TTOK/64, 1), 128>>>(
            pyh, pyl, pwh + OFF_OUT + (size_t)l*DMODEL*EINNER,
            pwl + OFF_OUT + (size_t)l*DMODEL*EINNER, dest,
            EINNER, EINNER, EINNER, DMODEL, nullptr, 0);
    }
}

// round 8
// speedup vs baseline: 3.2326x; 1.1153x over previous
#include <cuda_runtime.h>
#include <cuda_bf16.h>
#include <math.h>
#include <stdint.h>
#include <cstdint>

// ---------------- problem constants ----------------
#define NLAYERS 6
#define BATCH   2
#define LSEQ    1024
#define DMODEL  512
#define EINNER  1024
#define NSTATE  16
#define RRANK   32
#define RBC     64            // RRANK + 2*NSTATE
#define TTOK    (BATCH*LSEQ)  // 2048
#define NCHUNK  64
#define TCH     (LSEQ/NCHUNK) // 16
#define EPSF    1.1920929e-07f
#define L2E     1.4426950408889634f

// weight plane layout (bf16 hi/lo), element offsets
#define N_IN   (NLAYERS*2*EINNER*DMODEL)
#define N_XP   (NLAYERS*RBC*EINNER)
#define N_DT   (NLAYERS*EINNER*RRANK)
#define N_OUT  (NLAYERS*DMODEL*EINNER)
#define OFF_IN  0
#define OFF_XP  (N_IN)
#define OFF_DT  (N_IN+N_XP)
#define OFF_OUT (N_IN+N_XP+N_DT)
#define N_WTOT  (N_IN+N_XP+N_DT+N_OUT)

// ---------------- scratch ----------------
__device__ float g_h   [TTOK*DMODEL];
__device__ float g_xz  [TTOK*2*EINNER];
__device__ float g_xi  [TTOK*EINNER];
__device__ float g_dbcp[8*TTOK*RBC];
__device__ float g_dbc [TTOK*RBC];
__device__ float g_dt  [TTOK*EINNER];
__device__ float g_ya  [TTOK*EINNER];
__device__ float g_cum [TTOK*EINNER];
__device__ float g_hN  [BATCH*NCHUNK*EINNER*NSTATE];
__device__ float g_P   [BATCH*NCHUNK*EINNER*NSTATE];
__device__ float g_S   [BATCH*NCHUNK*EINNER*NSTATE];
__device__ __nv_bfloat16 g_wh [N_WTOT], g_wl [N_WTOT];
__device__ __nv_bfloat16 g_xnh[TTOK*DMODEL],  g_xnl[TTOK*DMODEL];
__device__ __nv_bfloat16 g_xih[TTOK*EINNER],  g_xil[TTOK*EINNER];
__device__ __nv_bfloat16 g_dbch[TTOK*RBC],    g_dbcl[TTOK*RBC];
__device__ __nv_bfloat16 g_yh [TTOK*EINNER],  g_yl [TTOK*EINNER];

__device__ __forceinline__ void split_bf16(float v, __nv_bfloat16& h, __nv_bfloat16& l) {
    h = __float2bfloat16(v);
    l = __float2bfloat16(v - __bfloat162float(h));
}

__device__ __forceinline__ float fexp2n(float x) {
    x = fmaxf(x, -126.0f);
    float t = x + 12582912.0f;
    int   i = __float_as_int(t) - 0x4B400000;
    float r = x - (t - 12582912.0f);
    float p =          1.3333558e-3f;
    p = fmaf(p, r, 9.6181291e-3f);
    p = fmaf(p, r, 5.5504109e-2f);
    p = fmaf(p, r, 2.4022651e-1f);
    p = fmaf(p, r, 6.9314718e-1f);
    p = fmaf(p, r, 1.0f);
    return __int_as_float(__float_as_int(p) + (i << 23));
}

__device__ __forceinline__ float softplusf(float x) {
    return fmaxf(x, 0.0f) + log1pf(__expf(-fabsf(x)));
}

#define LDSM4(r0,r1,r2,r3,addr) \
    asm volatile("ldmatrix.sync.aligned.m8n8.x4.shared.b16 {%0,%1,%2,%3}, [%4];" \
        : "=r"(r0), "=r"(r1), "=r"(r2), "=r"(r3) : "r"(addr))

#define CP16(dst_u32, src_ptr) \
    asm volatile("cp.async.cg.shared.global [%0], [%1], 16;" :: "r"(dst_u32), "l"(src_ptr))
#define CP_COMMIT() asm volatile("cp.async.commit_group;" ::: "memory")
#define CP_WAIT0()  asm volatile("cp.async.wait_group 0;" ::: "memory")

// ---------------- K0: weights -> bf16 hi/lo planes ----------------
__global__ void k_cvtw(const float* __restrict__ inw, const float* __restrict__ xpw,
                       const float* __restrict__ dtw, const float* __restrict__ outw,
                       __nv_bfloat16* __restrict__ wh, __nv_bfloat16* __restrict__ wl) {
    int i4 = blockIdx.x * blockDim.x + threadIdx.x;
    int e0 = i4 * 4;
    if (e0 >= N_WTOT) return;
    const float* src; int off;
    if      (e0 < OFF_XP)  { src = inw;  off = e0 - OFF_IN;  }
    else if (e0 < OFF_DT)  { src = xpw;  off = e0 - OFF_XP;  }
    else if (e0 < OFF_OUT) { src = dtw;  off = e0 - OFF_DT;  }
    else                   { src = outw; off = e0 - OFF_OUT; }
    float4 v = *(const float4*)(src + off);
    __nv_bfloat16 h0,h1,h2,h3,l0,l1,l2,l3;
    split_bf16(v.x,h0,l0); split_bf16(v.y,h1,l1);
    split_bf16(v.z,h2,l2); split_bf16(v.w,h3,l3);
    *(__nv_bfloat162*)&wh[e0]   = __nv_bfloat162(h0,h1);
    *(__nv_bfloat162*)&wh[e0+2] = __nv_bfloat162(h2,h3);
    *(__nv_bfloat162*)&wl[e0]   = __nv_bfloat162(l0,l1);
    *(__nv_bfloat162*)&wl[e0+2] = __nv_bfloat162(l2,l3);
}

// ---------------- K1: h+pos then RMSNorm -> bf16 hi/lo ----------------
__global__ void k_addnorm(const float* __restrict__ hin, const float* __restrict__ pos,
                          const float* __restrict__ nw,
                          __nv_bfloat16* __restrict__ oh, __nv_bfloat16* __restrict__ ol) {
    int t = blockIdx.x;
    int tid = threadIdx.x;
    float4 v  = ((const float4*)(hin + t*DMODEL))[tid];
    float4 pv = ((const float4*)(pos + t*DMODEL))[tid];
    v.x += pv.x; v.y += pv.y; v.z += pv.z; v.w += pv.w;
    float ss = v.x*v.x + v.y*v.y + v.z*v.z + v.w*v.w;
    #pragma unroll
    for (int o = 16; o > 0; o >>= 1) ss += __shfl_xor_sync(0xffffffffu, ss, o);
    __shared__ float sred[4];
    if ((tid & 31) == 0) sred[tid >> 5] = ss;
    __syncthreads();
    ss = sred[0] + sred[1] + sred[2] + sred[3];
    float s = rsqrtf(ss * (1.0f/DMODEL) + EPSF);
    float4 w = ((const float4*)nw)[tid];
    float o0 = v.x*s*w.x, o1 = v.y*s*w.y, o2 = v.z*s*w.z, o3 = v.w*s*w.w;
    __nv_bfloat16 h0,h1,h2,h3,l0,l1,l2,l3;
    split_bf16(o0,h0,l0); split_bf16(o1,h1,l1);
    split_bf16(o2,h2,l2); split_bf16(o3,h3,l3);
    int base = t*DMODEL + tid*4;
    *(__nv_bfloat162*)&oh[base]   = __nv_bfloat162(h0,h1);
    *(__nv_bfloat162*)&oh[base+2] = __nv_bfloat162(h2,h3);
    *(__nv_bfloat162*)&ol[base]   = __nv_bfloat162(l0,l1);
    *(__nv_bfloat162*)&ol[base+2] = __nv_bfloat162(l2,l3);
}

// ---------------- bf16-split MMA GEMM, cp.async double-buffered ----------------
__device__ __forceinline__ void mma_bf16(float (&d)[4], const unsigned (&a)[4],
                                         const unsigned (&b)[2]) {
    asm volatile(
        "mma.sync.aligned.m16n8k16.row.col.f32.bf16.bf16.f32 "
        "{%0,%1,%2,%3}, {%4,%5,%6,%7}, {%8,%9}, {%0,%1,%2,%3};\n"
        : "+f"(d[0]), "+f"(d[1]), "+f"(d[2]), "+f"(d[3])
        : "r"(a[0]), "r"(a[1]), "r"(a[2]), "r"(a[3]), "r"(b[0]), "r"(b[1]));
}

// BM=BN=64, 4 warps (128 thr), BK=32, 3-term bf16-split, cp.async double buffer, LDSM.
template<int EPI>
__global__ void __launch_bounds__(128)
k_mma(const __nv_bfloat16* __restrict__ Agh, const __nv_bfloat16* __restrict__ Agl,
      const __nv_bfloat16* __restrict__ Bgh, const __nv_bfloat16* __restrict__ Bgl,
      float* __restrict__ C, int K, int lda, int ldw, int ldc,
      const float* __restrict__ bias, int pstride)
{
    constexpr int BM = 64, BN = 64, BK = 32, THREADS = 128;
    constexpr int TM = 2, TN = 4;
    constexpr int LST = BK + 8;                 // 40 bf16 per smem row (80B)
    constexpr int BUFB = BM*LST*2;              // bytes per buffer per plane

    __shared__ __align__(16) __nv_bfloat16 Ah[2][BM*LST], Al[2][BM*LST];
    __shared__ __align__(16) __nv_bfloat16 Bh[2][BN*LST], Bl[2][BN*LST];

    const int tid  = threadIdx.x;
    const int lane = tid & 31;
    const int warp = tid >> 5;
    const int wm = (warp >> 1) * 32;
    const int wn = (warp & 1) * 32;
    const int m0 = blockIdx.y * BM, n0 = blockIdx.x * BN;
    const int kLen = K / gridDim.z;
    const int k0 = blockIdx.z * kLen;
    const int niter = kLen / BK;

    const int laneq = lane & 7;
    const int a_rowoff = (wm + laneq + ((lane>>3)&1)*8) * LST;
    const int a_koff   = (lane>>4)*8;
    const int b_rowoff = (wn + (lane>>4)*8 + laneq) * LST;
    const int b_koff   = ((lane>>3)&1)*8;

    const unsigned uAh = (unsigned)__cvta_generic_to_shared(&Ah[0][0]);
    const unsigned uAl = (unsigned)__cvta_generic_to_shared(&Al[0][0]);
    const unsigned uBh = (unsigned)__cvta_generic_to_shared(&Bh[0][0]);
    const unsigned uBl = (unsigned)__cvta_generic_to_shared(&Bl[0][0]);

    float acc[TM][TN][4];
    #pragma unroll
    for (int i = 0; i < TM; i++)
        #pragma unroll
        for (int j = 0; j < TN; j++)
            #pragma unroll
            for (int q = 0; q < 4; q++) acc[i][j][q] = 0.0f;

    const int r_  = tid >> 2,             kc_  = tid & 3;
    const int r2_ = (tid + THREADS) >> 2, kc2_ = (tid + THREADS) & 3;
    const int o0b = (r_*LST + kc_*8) * 2, o1b = (r2_*LST + kc2_*8) * 2;  // byte offs

    auto issue_tile = [&](int buf, int kb) {
        const int bb = buf * BUFB;
        size_t gA0 = (size_t)(m0 + r_ ) * lda + kb + kc_ *8;
        size_t gA1 = (size_t)(m0 + r2_) * lda + kb + kc2_*8;
        size_t gB0 = (size_t)(n0 + r_ ) * ldw + kb + kc_ *8;
        size_t gB1 = (size_t)(n0 + r2_) * ldw + kb + kc2_*8;
        CP16(uAh + bb + o0b, &Agh[gA0]);
        CP16(uAl + bb + o0b, &Agl[gA0]);
        CP16(uAh + bb + o1b, &Agh[gA1]);
        CP16(uAl + bb + o1b, &Agl[gA1]);
        CP16(uBh + bb + o0b, &Bgh[gB0]);
        CP16(uBl + bb + o0b, &Bgl[gB0]);
        CP16(uBh + bb + o1b, &Bgh[gB1]);
        CP16(uBl + bb + o1b, &Bgl[gB1]);
        CP_COMMIT();
    };

    issue_tile(0, k0);
    CP_WAIT0();
    __syncthreads();

    for (int kt = 0; kt < niter; kt++) {
        const int cur = kt & 1;
        const bool more = (kt + 1 < niter);
        if (more) issue_tile(cur ^ 1, k0 + (kt+1)*BK);   // overlaps with MMA below

        const int bufB = cur * BUFB;
        #pragma unroll
        for (int s = 0; s < 2; s++) {
            unsigned bhf[TN][2], blf[TN][2];
            {
                int boff = bufB + (b_rowoff + s*16 + b_koff) * 2;
                unsigned t0,t1,t2,t3;
                LDSM4(t0,t1,t2,t3, uBh + boff);
                bhf[0][0]=t0; bhf[0][1]=t1; bhf[1][0]=t2; bhf[1][1]=t3;
                LDSM4(t0,t1,t2,t3, uBh + boff + 16*LST*2);
                bhf[2][0]=t0; bhf[2][1]=t1; bhf[3][0]=t2; bhf[3][1]=t3;
                LDSM4(t0,t1,t2,t3, uBl + boff);
                blf[0][0]=t0; blf[0][1]=t1; blf[1][0]=t2; blf[1][1]=t3;
                LDSM4(t0,t1,t2,t3, uBl + boff + 16*LST*2);
                blf[2][0]=t0; blf[2][1]=t1; blf[3][0]=t2; blf[3][1]=t3;
            }
            #pragma unroll
            for (int i = 0; i < TM; i++) {
                int aoff = bufB + (a_rowoff + i*16*LST + s*16 + a_koff) * 2;
                unsigned ahf[4], alf[4];
                LDSM4(ahf[0],ahf[1],ahf[2],ahf[3], uAh + aoff);
                LDSM4(alf[0],alf[1],alf[2],alf[3], uAl + aoff);
                #pragma unroll
                for (int j = 0; j < TN; j++) {
                    mma_bf16(acc[i][j], ahf, bhf[j]);
                    mma_bf16(acc[i][j], ahf, blf[j]);
                    mma_bf16(acc[i][j], alf, bhf[j]);
                }
            }
        }

        if (more) { CP_WAIT0(); }
        __syncthreads();
    }

    float* Cp = C + (size_t)blockIdx.z * pstride;
    #pragma unroll
    for (int i = 0; i < TM; i++) {
        int row = m0 + wm + i*16 + (lane >> 2);
        #pragma unroll
        for (int j = 0; j < TN; j++) {
            int col = n0 + wn + j*8 + (lane & 3)*2;
            float2 v0, v1;
            if (EPI == 1) {
                float b0 = bias[col], b1 = bias[col+1];
                v0.x = softplusf(acc[i][j][0] + b0);
                v0.y = softplusf(acc[i][j][1] + b1);
                v1.x = softplusf(acc[i][j][2] + b0);
                v1.y = softplusf(acc[i][j][3] + b1);
            } else {
                v0.x = acc[i][j][0]; v0.y = acc[i][j][1];
                v1.x = acc[i][j][2]; v1.y = acc[i][j][3];
            }
            *(float2*)&Cp[(size_t)row * ldc + col]     = v0;
            *(float2*)&Cp[(size_t)(row+8) * ldc + col] = v1;
        }
    }
}

// ---------------- K3: causal depthwise conv (k=4) + bias + SiLU ----------------
__global__ void k_conv(const float* __restrict__ xz, const float* __restrict__ cw,
                       const float* __restrict__ cb, float* __restrict__ xi,
                       __nv_bfloat16* __restrict__ xih, __nv_bfloat16* __restrict__ xil) {
    int idx = blockIdx.x * blockDim.x + threadIdx.x;
    int e  = idx & (EINNER - 1);
    int lg = (idx >> 10) & (LSEQ/4 - 1);
    int b  = idx >> 18;
    int l0 = lg * 4;
    const float* base = xz + (size_t)(b * LSEQ) * 2 * EINNER + e;
    float xv[7];
    #pragma unroll
    for (int j = 0; j < 7; j++) {
        int li = l0 - 3 + j;
        xv[j] = (li >= 0) ? base[(size_t)li * 2 * EINNER] : 0.0f;
    }
    float w0 = cw[e*4+0], w1 = cw[e*4+1], w2 = cw[e*4+2], w3 = cw[e*4+3];
    float bb = cb[e];
    #pragma unroll
    for (int t = 0; t < 4; t++) {
        float acc = bb;
        acc = fmaf(w0, xv[t+0], acc);
        acc = fmaf(w1, xv[t+1], acc);
        acc = fmaf(w2, xv[t+2], acc);
        acc = fmaf(w3, xv[t+3], acc);
        float v = acc / (1.0f + __expf(-acc));
        size_t oi = (size_t)(b*LSEQ + l0 + t) * EINNER + e;
        xi[oi] = v;
        __nv_bfloat16 h, lo; split_bf16(v, h, lo);
        xih[oi] = h; xil[oi] = lo;
    }
}

// ---------------- split-K reduce for x_proj (+ bf16 planes) ----------------
__global__ void k_reduce8(const float* __restrict__ part, float* __restrict__ out,
                          __nv_bfloat16* __restrict__ oh, __nv_bfloat16* __restrict__ ol,
                          int n) {
    int i = blockIdx.x * blockDim.x + threadIdx.x;
    if (i < n) {
        float s = 0.f;
        #pragma unroll
        for (int z = 0; z < 8; z++) s += part[(size_t)z * n + i];
        out[i] = s;
        __nv_bfloat16 h, lo; split_bf16(s, h, lo);
        oh[i] = h; ol[i] = lo;
    }
}

// ---------------- A setup helper ----------------
__device__ __forceinline__ bool load_A(const float* __restrict__ Alog, int e,
                                       float (&A2)[NSTATE]) {
    bool st = true;
    float A0 = -__expf(Alog[e*NSTATE]);
    #pragma unroll
    for (int n = 0; n < NSTATE; n++) {
        float An = -__expf(Alog[e*NSTATE + n]);
        A2[n] = An * L2E;
        st = st && (fabsf(An - (n+1)*A0) <= 1e-5f * fabsf(An));
    }
    return st;
}

// ---------------- scan pass 1 ----------------
__global__ void k_scan1(const float* __restrict__ dt, const float* __restrict__ u,
                        const float* __restrict__ dbc, const float* __restrict__ Alog,
                        float* __restrict__ hN, float* __restrict__ P,
                        float* __restrict__ yacc, float* __restrict__ cum) {
    int e = blockIdx.x * 128 + threadIdx.x;
    int c = blockIdx.y, b = blockIdx.z;
    int rowbase = b * LSEQ + c * TCH;
    __shared__ float sBC[TCH][2*NSTATE];
    for (int i = threadIdx.x; i < TCH*2*NSTATE; i += 128) {
        int r = i >> 5, n = i & 31;
        sBC[r][n] = dbc[(size_t)(rowbase + r) * RBC + RRANK + n];
    }
    float A2[NSTATE];
    bool st = load_A(Alog, e, A2);
    __syncthreads();

    float h[NSTATE];
    #pragma unroll
    for (int n = 0; n < NSTATE; n++) h[n] = 0.f;
    float cumd = 0.f;
    for (int tt = 0; tt < TCH; tt++) {
        int row = rowbase + tt;
        float d  = dt[(size_t)row * EINNER + e];
        float uu = u [(size_t)row * EINNER + e];
        float du = d * uu;
        float acc = 0.f;
        if (st) {
            float w = fexp2n(d * A2[0]);
            float a = 1.0f;
            #pragma unroll
            for (int n = 0; n < NSTATE; n++) {
                a *= w;
                h[n] = fmaf(a, h[n], du * sBC[tt][n]);
                acc = fmaf(h[n], sBC[tt][NSTATE + n], acc);
            }
        } else {
            #pragma unroll
            for (int n = 0; n < NSTATE; n++) {
                float a = fexp2n(d * A2[n]);
                h[n] = fmaf(a, h[n], du * sBC[tt][n]);
                acc = fmaf(h[n], sBC[tt][NSTATE + n], acc);
            }
        }
        cumd += d;
        size_t oi = (size_t)row * EINNER + e;
        yacc[oi] = acc;
        cum[oi]  = cumd;
    }
    int o = ((b * NCHUNK + c) * EINNER + e) * NSTATE;
    if (st) {
        float ws = fexp2n(cumd * A2[0]);
        float a = 1.0f;
        #pragma unroll
        for (int n = 0; n < NSTATE; n++) { a *= ws; hN[o+n] = h[n]; P[o+n] = a; }
    } else {
        #pragma unroll
        for (int n = 0; n < NSTATE; n++) { hN[o+n] = h[n]; P[o+n] = fexp2n(cumd * A2[n]); }
    }
}

// ---------------- scan pass 2 ----------------
__global__ void k_scan2(const float* __restrict__ hN, const float* __restrict__ P,
                        float* __restrict__ S) {
    int idx = blockIdx.x * blockDim.x + threadIdx.x;
    int b = idx >> 14;
    int r = idx & 16383;
    float s = 0.f;
    int base = b * NCHUNK * EINNER * NSTATE + r;
    #pragma unroll 8
    for (int c = 0; c < NCHUNK; c++) {
        S[base + c * EINNER * NSTATE] = s;
        s = hN[base + c * EINNER * NSTATE] + P[base + c * EINNER * NSTATE] * s;
    }
}

// ---------------- scan pass 3: parallel correction ----------------
__global__ void k_scan3(const float* __restrict__ u, const float* __restrict__ dbc,
                        const float* __restrict__ xz, const float* __restrict__ Alog,
                        const float* __restrict__ Dv, const float* __restrict__ S,
                        const float* __restrict__ yacc, const float* __restrict__ cum,
                        __nv_bfloat16* __restrict__ yh, __nv_bfloat16* __restrict__ yl) {
    int e = blockIdx.x * 128 + threadIdx.x;
    int c = blockIdx.y, b = blockIdx.z;
    int rowbase = b * LSEQ + c * TCH;
    __shared__ float sC[TCH][NSTATE];
    for (int i = threadIdx.x; i < TCH*NSTATE; i += 128) {
        int r = i >> 4, n = i & 15;
        sC[r][n] = dbc[(size_t)(rowbase + r) * RBC + RRANK + NSTATE + n];
    }
    float A2[NSTATE];
    bool st = load_A(Alog, e, A2);
    float Dd = Dv[e];
    float sreg[NSTATE];
    int o = ((b * NCHUNK + c) * EINNER + e) * NSTATE;
    #pragma unroll
    for (int n = 0; n < NSTATE; n++) sreg[n] = S[o + n];
    __syncthreads();

    for (int tt = 0; tt < TCH; tt++) {
        int row = rowbase + tt;
        size_t oi = (size_t)row * EINNER + e;
        float cd = cum[oi];
        float acc = yacc[oi];
        float uu  = u[oi];
        float zz  = xz[(size_t)row * 2 * EINNER + EINNER + e];
        if (st) {
            float wS = fexp2n(cd * A2[0]);
            float a = 1.0f;
            #pragma unroll
            for (int n = 0; n < NSTATE; n++) {
                a *= wS;
                acc = fmaf(a * sreg[n], sC[tt][n], acc);
            }
        } else {
            #pragma unroll
            for (int n = 0; n < NSTATE; n++)
                acc = fmaf(fexp2n(cd * A2[n]) * sreg[n], sC[tt][n], acc);
        }
        acc = fmaf(uu, Dd, acc);
        float sz = zz / (1.0f + __expf(-zz));
        float yv = acc * sz;
        __nv_bfloat16 hh, ll; split_bf16(yv, hh, ll);
        yh[oi] = hh; yl[oi] = ll;
    }
}

// ---------------- launcher ----------------
extern "C" void kernel_launch(void* const* d_in, const int* in_sizes, int n_in,
                              void* d_out, int out_size) {
    const float* x     = (const float*)d_in[0];
    const float* pos   = (const float*)d_in[1];
    const float* normw = (const float*)d_in[2];
    const float* inw   = (const float*)d_in[3];
    const float* convw = (const float*)d_in[4];
    const float* convb = (const float*)d_in[5];
    const float* xpw   = (const float*)d_in[6];
    const float* dtw   = (const float*)d_in[7];
    const float* dtb   = (const float*)d_in[8];
    const float* alog  = (const float*)d_in[9];
    const float* dvec  = (const float*)d_in[10];
    const float* outw  = (const float*)d_in[11];
    float* out = (float*)d_out;
    (void)in_sizes; (void)n_in; (void)out_size;

    float *ph, *pxz, *pxi, *pdbcp, *pdbc, *pdt, *pya, *pcum, *phN, *pP, *pS;
    __nv_bfloat16 *pwh, *pwl, *pxnh, *pxnl, *pxih, *pxil, *pdbch, *pdbcl, *pyh, *pyl;
    cudaGetSymbolAddress((void**)&ph,    g_h);
    cudaGetSymbolAddress((void**)&pxz,   g_xz);
    cudaGetSymbolAddress((void**)&pxi,   g_xi);
    cudaGetSymbolAddress((void**)&pdbcp, g_dbcp);
    cudaGetSymbolAddress((void**)&pdbc,  g_dbc);
    cudaGetSymbolAddress((void**)&pdt,   g_dt);
    cudaGetSymbolAddress((void**)&pya,   g_ya);
    cudaGetSymbolAddress((void**)&pcum,  g_cum);
    cudaGetSymbolAddress((void**)&phN,   g_hN);
    cudaGetSymbolAddress((void**)&pP,    g_P);
    cudaGetSymbolAddress((void**)&pS,    g_S);
    cudaGetSymbolAddress((void**)&pwh,   g_wh);
    cudaGetSymbolAddress((void**)&pwl,   g_wl);
    cudaGetSymbolAddress((void**)&pxnh,  g_xnh);
    cudaGetSymbolAddress((void**)&pxnl,  g_xnl);
    cudaGetSymbolAddress((void**)&pxih,  g_xih);
    cudaGetSymbolAddress((void**)&pxil,  g_xil);
    cudaGetSymbolAddress((void**)&pdbch, g_dbch);
    cudaGetSymbolAddress((void**)&pdbcl, g_dbcl);
    cudaGetSymbolAddress((void**)&pyh,   g_yh);
    cudaGetSymbolAddress((void**)&pyl,   g_yl);

    k_cvtw<<<(N_WTOT/4 + 255)/256, 256>>>(inw, xpw, dtw, outw, pwh, pwl);

    for (int l = 0; l < NLAYERS; l++) {
        const float* hin = (l == 0) ? x : ph;
        // 1. h+pos -> rmsnorm -> xn planes
        k_addnorm<<<TTOK, 128>>>(hin, pos, normw, pxnh, pxnl);
        // 2. in_proj -> xz fp32 (2048,2048)
        k_mma<0><<<dim3(2*EINNER/64, TTOK/64, 1), 128>>>(
            pxnh, pxnl, pwh + OFF_IN + (size_t)l*2*EINNER*DMODEL,
            pwl + OFF_IN + (size_t)l*2*EINNER*DMODEL, pxz,
            DMODEL, DMODEL, DMODEL, 2*EINNER, nullptr, 0);
        // 3. conv + SiLU -> xi fp32 + planes
        k_conv<<<(TTOK*EINNER/4)/256, 256>>>(pxz, convw + (size_t)l*EINNER*4,
                                             convb + (size_t)l*EINNER, pxi, pxih, pxil);
        // 4. x_proj split-K=8 + reduce -> dbc fp32 + planes
        k_mma<0><<<dim3(1, TTOK/64, 8), 128>>>(
            pxih, pxil, pwh + OFF_XP + (size_t)l*RBC*EINNER,
            pwl + OFF_XP + (size_t)l*RBC*EINNER, pdbcp,
            EINNER, EINNER, EINNER, RBC, nullptr, TTOK*RBC);
        k_reduce8<<<(TTOK*RBC)/256, 256>>>(pdbcp, pdbc, pdbch, pdbcl, TTOK*RBC);
        // 5. dt_proj + softplus(+bias) -> dt fp32
        k_mma<1><<<dim3(EINNER/64, TTOK/64, 1), 128>>>(
            pdbch, pdbcl, pwh + OFF_DT + (size_t)l*EINNER*RRANK,
            pwl + OFF_DT + (size_t)l*EINNER*RRANK, pdt,
            RRANK, RBC, RRANK, EINNER, dtb + (size_t)l*EINNER, 0);
        // 6. scan: sequential pass + combine + parallel correction
        k_scan1<<<dim3(EINNER/128, NCHUNK, BATCH), 128>>>(pdt, pxi, pdbc,
                                                          alog + (size_t)l*EINNER*NSTATE,
                                                          phN, pP, pya, pcum);
        k_scan2<<<(BATCH*EINNER*NSTATE)/256, 256>>>(phN, pP, pS);
        k_scan3<<<dim3(EINNER/128, NCHUNK, BATCH), 128>>>(pxi, pdbc, pxz,
                                                          alog + (size_t)l*EINNER*NSTATE,
                                                          dvec + (size_t)l*EINNER, pS,
                                                          pya, pcum, pyh, pyl);
        // 7. out_proj -> next h (or final output)
        float* dest = (l == NLAYERS-1) ? out : ph;
        k_mma<0><<<dim3(DMODEL/64, TTOK/64, 1), 128>>>(
            pyh, pyl, pwh + OFF_OUT + (size_t)l*DMODEL*EINNER,
            pwl + OFF_OUT + (size_t)l*DMODEL*EINNER, dest,
            EINNER, EINNER, EINNER, DMODEL, nullptr, 0);
    }
}